// round 1
// baseline (speedup 1.0000x reference)
#include <cuda_runtime.h>
#include <math_constants.h>

#define SLEN 2048
#define BATCH 4
#define DMODEL 1024
#define NHEAD 16
#define DKH 64
#define DFFN 4096
#define NTOK (SLEN*BATCH)   // 8192
#define LN_EPS 1e-5f

// ---------------- scratch (device globals: allocation-guard safe) ----------
__device__ float g_Q[NTOK*DMODEL];
__device__ float g_K[NTOK*DMODEL];
__device__ float g_V[NTOK*DMODEL];
__device__ float g_CTX[NTOK*DMODEL];
__device__ float g_Y[NTOK*DMODEL];
__device__ float g_X1[NTOK*DMODEL];
__device__ float g_HID[NTOK*DFFN];
__device__ float g_M[NTOK*DMODEL];

// ---------------- GEMM: C[M,N] = A[M,K] @ Bw[N,K]^T + bias (opt ReLU) ------
// Tiles: BM=BN=128, BK=16. 256 threads, 8x8 accumulators per thread.
template<int RELU>
__global__ void __launch_bounds__(256) gemm_tn_kernel(
    const float* __restrict__ A, const float* __restrict__ Bw,
    const float* __restrict__ bias, float* __restrict__ C,
    int M, int N, int K)
{
    const int BM = 128, BN = 128, BK = 16;
    __shared__ float As[BK][BM + 4];
    __shared__ float Bs[BK][BN + 4];

    const int bm = blockIdx.y * BM;
    const int bn = blockIdx.x * BN;
    const int tid = threadIdx.x;
    const int tx = tid & 15;       // 0..15 -> n
    const int ty = tid >> 4;       // 0..15 -> m
    const int lrow = tid >> 1;     // 0..127
    const int lcol = (tid & 1) * 8;

    float acc[8][8];
#pragma unroll
    for (int i = 0; i < 8; i++)
#pragma unroll
        for (int j = 0; j < 8; j++) acc[i][j] = 0.f;

    const float* aptr = A + (size_t)(bm + lrow) * K + lcol;
    const float* bptr = Bw + (size_t)(bn + lrow) * K + lcol;

    for (int k0 = 0; k0 < K; k0 += BK) {
        float4 a0 = *(const float4*)(aptr + k0);
        float4 a1 = *(const float4*)(aptr + k0 + 4);
        float4 b0 = *(const float4*)(bptr + k0);
        float4 b1 = *(const float4*)(bptr + k0 + 4);
        As[lcol + 0][lrow] = a0.x; As[lcol + 1][lrow] = a0.y;
        As[lcol + 2][lrow] = a0.z; As[lcol + 3][lrow] = a0.w;
        As[lcol + 4][lrow] = a1.x; As[lcol + 5][lrow] = a1.y;
        As[lcol + 6][lrow] = a1.z; As[lcol + 7][lrow] = a1.w;
        Bs[lcol + 0][lrow] = b0.x; Bs[lcol + 1][lrow] = b0.y;
        Bs[lcol + 2][lrow] = b0.z; Bs[lcol + 3][lrow] = b0.w;
        Bs[lcol + 4][lrow] = b1.x; Bs[lcol + 5][lrow] = b1.y;
        Bs[lcol + 6][lrow] = b1.z; Bs[lcol + 7][lrow] = b1.w;
        __syncthreads();

#pragma unroll
        for (int kk = 0; kk < BK; kk++) {
            float ar[8], br[8];
            float4 av0 = *(const float4*)&As[kk][ty * 8];
            float4 av1 = *(const float4*)&As[kk][ty * 8 + 4];
            float4 bv0 = *(const float4*)&Bs[kk][tx * 8];
            float4 bv1 = *(const float4*)&Bs[kk][tx * 8 + 4];
            ar[0]=av0.x; ar[1]=av0.y; ar[2]=av0.z; ar[3]=av0.w;
            ar[4]=av1.x; ar[5]=av1.y; ar[6]=av1.z; ar[7]=av1.w;
            br[0]=bv0.x; br[1]=bv0.y; br[2]=bv0.z; br[3]=bv0.w;
            br[4]=bv1.x; br[5]=bv1.y; br[6]=bv1.z; br[7]=bv1.w;
#pragma unroll
            for (int i = 0; i < 8; i++)
#pragma unroll
                for (int j = 0; j < 8; j++)
                    acc[i][j] = fmaf(ar[i], br[j], acc[i][j]);
        }
        __syncthreads();
    }

    // epilogue
#pragma unroll
    for (int i = 0; i < 8; i++) {
        int m = bm + ty * 8 + i;
        float* cp = C + (size_t)m * N + bn + tx * 8;
        float4 o0, o1;
        const float* bp = bias + bn + tx * 8;
        o0.x = acc[i][0] + bp[0]; o0.y = acc[i][1] + bp[1];
        o0.z = acc[i][2] + bp[2]; o0.w = acc[i][3] + bp[3];
        o1.x = acc[i][4] + bp[4]; o1.y = acc[i][5] + bp[5];
        o1.z = acc[i][6] + bp[6]; o1.w = acc[i][7] + bp[7];
        if (RELU) {
            o0.x = fmaxf(o0.x, 0.f); o0.y = fmaxf(o0.y, 0.f);
            o0.z = fmaxf(o0.z, 0.f); o0.w = fmaxf(o0.w, 0.f);
            o1.x = fmaxf(o1.x, 0.f); o1.y = fmaxf(o1.y, 0.f);
            o1.z = fmaxf(o1.z, 0.f); o1.w = fmaxf(o1.w, 0.f);
        }
        *(float4*)cp = o0;
        *(float4*)(cp + 4) = o1;
    }
}

// ---------------- Flash attention (non-causal, full 2048 keys) -------------
// grid = (SLEN/64, BATCH*NHEAD), 256 threads.
// Qs,Ks stored transposed [k][m]; Vs natural [n][dv]; Ps natural [m][n].
#define TP 68
__global__ void __launch_bounds__(256) attn_kernel(
    const float* __restrict__ Qg, const float* __restrict__ Kg,
    const float* __restrict__ Vg, float* __restrict__ Og)
{
    extern __shared__ float sm[];
    float* Qs = sm;                // [64][TP]  Qs[k][m]
    float* Ks = Qs + 64 * TP;      // [64][TP]  Ks[k][n]
    float* Vs = Ks + 64 * TP;      // [64][TP]  Vs[n][dv]
    float* Ps = Vs + 64 * TP;      // [64][TP]  Ps[m][n]

    const int tid = threadIdx.x;
    const int q0 = blockIdx.x * 64;
    const int b = blockIdx.y / NHEAD;
    const int h = blockIdx.y % NHEAD;
    const int lr = tid >> 2;          // 0..63
    const int lc = (tid & 3) * 16;    // 0,16,32,48
    const int tx = tid & 15;          // key/dv group
    const int ty = tid >> 4;          // query-row group

    const int headoff = h * DKH;

    // load Q tile (pre-scaled by 1/sqrt(dk)=0.125), transposed
    {
        const float* qp = Qg + ((size_t)(q0 + lr) * BATCH + b) * DMODEL + headoff + lc;
#pragma unroll
        for (int i = 0; i < 16; i += 4) {
            float4 v = *(const float4*)(qp + i);
            Qs[(lc + i + 0) * TP + lr] = v.x * 0.125f;
            Qs[(lc + i + 1) * TP + lr] = v.y * 0.125f;
            Qs[(lc + i + 2) * TP + lr] = v.z * 0.125f;
            Qs[(lc + i + 3) * TP + lr] = v.w * 0.125f;
        }
    }

    float m_i[4], l_i[4], acc[4][4];
#pragma unroll
    for (int r = 0; r < 4; r++) {
        m_i[r] = -1e30f; l_i[r] = 0.f;
#pragma unroll
        for (int c = 0; c < 4; c++) acc[r][c] = 0.f;
    }

    for (int kt = 0; kt < SLEN / 64; kt++) {
        __syncthreads();   // protect Ks/Vs/Ps from previous iteration readers
        {
            const float* kp = Kg + ((size_t)(kt * 64 + lr) * BATCH + b) * DMODEL + headoff + lc;
            const float* vp = Vg + ((size_t)(kt * 64 + lr) * BATCH + b) * DMODEL + headoff + lc;
#pragma unroll
            for (int i = 0; i < 16; i += 4) {
                float4 v = *(const float4*)(kp + i);
                Ks[(lc + i + 0) * TP + lr] = v.x;
                Ks[(lc + i + 1) * TP + lr] = v.y;
                Ks[(lc + i + 2) * TP + lr] = v.z;
                Ks[(lc + i + 3) * TP + lr] = v.w;
                float4 w = *(const float4*)(vp + i);
                *(float4*)&Vs[lr * TP + lc + i] = w;
            }
        }
        __syncthreads();

        // scores: sc[r][c] = sum_k Qs[k][m] * Ks[k][n]
        float sc[4][4];
#pragma unroll
        for (int r = 0; r < 4; r++)
#pragma unroll
            for (int c = 0; c < 4; c++) sc[r][c] = 0.f;

#pragma unroll 8
        for (int k = 0; k < 64; k++) {
            float4 qa = *(const float4*)&Qs[k * TP + ty * 4];
            float4 kb = *(const float4*)&Ks[k * TP + tx * 4];
            float qr[4] = {qa.x, qa.y, qa.z, qa.w};
            float kr[4] = {kb.x, kb.y, kb.z, kb.w};
#pragma unroll
            for (int r = 0; r < 4; r++)
#pragma unroll
                for (int c = 0; c < 4; c++)
                    sc[r][c] = fmaf(qr[r], kr[c], sc[r][c]);
        }

        // online softmax (row groups of 16 lanes share a row)
        float p[4][4];
#pragma unroll
        for (int r = 0; r < 4; r++) {
            float mloc = sc[r][0];
            mloc = fmaxf(mloc, sc[r][1]);
            mloc = fmaxf(mloc, sc[r][2]);
            mloc = fmaxf(mloc, sc[r][3]);
#pragma unroll
            for (int off = 8; off >= 1; off >>= 1)
                mloc = fmaxf(mloc, __shfl_xor_sync(0xffffffffu, mloc, off));
            float mnew = fmaxf(m_i[r], mloc);
            float alpha = __expf(m_i[r] - mnew);
            m_i[r] = mnew;
            float ls = 0.f;
#pragma unroll
            for (int c = 0; c < 4; c++) {
                p[r][c] = __expf(sc[r][c] - mnew);
                ls += p[r][c];
            }
#pragma unroll
            for (int off = 8; off >= 1; off >>= 1)
                ls += __shfl_xor_sync(0xffffffffu, ls, off);
            l_i[r] = l_i[r] * alpha + ls;
#pragma unroll
            for (int c = 0; c < 4; c++) acc[r][c] *= alpha;
        }

        // stage P natural [m][n] (vectorized store)
#pragma unroll
        for (int r = 0; r < 4; r++) {
            float4 pv = make_float4(p[r][0], p[r][1], p[r][2], p[r][3]);
            *(float4*)&Ps[(ty * 4 + r) * TP + tx * 4] = pv;
        }
        __syncthreads();

        // acc[r][c] += sum_n Ps[m][n] * Vs[n][dv]
#pragma unroll 8
        for (int k = 0; k < 64; k++) {
            float4 vb = *(const float4*)&Vs[k * TP + tx * 4];
            float vr[4] = {vb.x, vb.y, vb.z, vb.w};
#pragma unroll
            for (int r = 0; r < 4; r++) {
                float pa = Ps[(ty * 4 + r) * TP + k];
#pragma unroll
                for (int c = 0; c < 4; c++)
                    acc[r][c] = fmaf(pa, vr[c], acc[r][c]);
            }
        }
    }

    // write ctx
#pragma unroll
    for (int r = 0; r < 4; r++) {
        float inv = 1.0f / l_i[r];
        int m = ty * 4 + r;
        float* op = Og + ((size_t)(q0 + m) * BATCH + b) * DMODEL + headoff + tx * 4;
        float4 o = make_float4(acc[r][0] * inv, acc[r][1] * inv,
                               acc[r][2] * inv, acc[r][3] * inv);
        *(float4*)op = o;
    }
}

// ---------------- fused residual add + LayerNorm ---------------------------
// one block per token row, 256 threads x 4 elements
__global__ void __launch_bounds__(256) add_ln_kernel(
    const float* __restrict__ A, const float* __restrict__ R,
    const float* __restrict__ gam, const float* __restrict__ bet,
    float* __restrict__ out)
{
    __shared__ float red_s[8];
    __shared__ float red_ss[8];
    __shared__ float s_mu, s_rstd;
    const int row = blockIdx.x;
    const int t = threadIdx.x;
    const float4* a4 = (const float4*)(A + (size_t)row * DMODEL);
    const float4* r4 = (const float4*)(R + (size_t)row * DMODEL);
    float4 v = a4[t];
    float4 w = r4[t];
    v.x += w.x; v.y += w.y; v.z += w.z; v.w += w.w;
    float s = v.x + v.y + v.z + v.w;
    float ss = v.x * v.x + v.y * v.y + v.z * v.z + v.w * v.w;
#pragma unroll
    for (int off = 16; off >= 1; off >>= 1) {
        s += __shfl_xor_sync(0xffffffffu, s, off);
        ss += __shfl_xor_sync(0xffffffffu, ss, off);
    }
    if ((t & 31) == 0) { red_s[t >> 5] = s; red_ss[t >> 5] = ss; }
    __syncthreads();
    if (t == 0) {
        float ts = 0.f, tss = 0.f;
#pragma unroll
        for (int i = 0; i < 8; i++) { ts += red_s[i]; tss += red_ss[i]; }
        float mu = ts * (1.0f / DMODEL);
        float var = tss * (1.0f / DMODEL) - mu * mu;
        s_mu = mu;
        s_rstd = rsqrtf(var + LN_EPS);
    }
    __syncthreads();
    float mu = s_mu, rs = s_rstd;
    const float4* g4 = (const float4*)gam;
    const float4* b4 = (const float4*)bet;
    float4 g = g4[t], bb = b4[t];
    float4 o;
    o.x = (v.x - mu) * rs * g.x + bb.x;
    o.y = (v.y - mu) * rs * g.y + bb.y;
    o.z = (v.z - mu) * rs * g.z + bb.z;
    o.w = (v.w - mu) * rs * g.w + bb.w;
    ((float4*)(out + (size_t)row * DMODEL))[t] = o;
}

// ---------------- launch ----------------------------------------------------
extern "C" void kernel_launch(void* const* d_in, const int* in_sizes, int n_in,
                              void* d_out, int out_size)
{
    const float* X    = (const float*)d_in[0];
    const float* WQw  = (const float*)d_in[1];
    const float* WQb  = (const float*)d_in[2];
    const float* WKw  = (const float*)d_in[3];
    const float* WKb  = (const float*)d_in[4];
    const float* WVw  = (const float*)d_in[5];
    const float* WVb  = (const float*)d_in[6];
    const float* WOw  = (const float*)d_in[7];
    const float* WOb  = (const float*)d_in[8];
    const float* ln1g = (const float*)d_in[9];
    const float* ln1b = (const float*)d_in[10];
    const float* W1   = (const float*)d_in[11];
    const float* b1   = (const float*)d_in[12];
    const float* W2   = (const float*)d_in[13];
    const float* b2   = (const float*)d_in[14];
    const float* ln2g = (const float*)d_in[15];
    const float* ln2b = (const float*)d_in[16];
    float* out = (float*)d_out;

    float *Q, *K, *V, *CTX, *Y, *X1, *HID, *M;
    cudaGetSymbolAddress((void**)&Q,   g_Q);
    cudaGetSymbolAddress((void**)&K,   g_K);
    cudaGetSymbolAddress((void**)&V,   g_V);
    cudaGetSymbolAddress((void**)&CTX, g_CTX);
    cudaGetSymbolAddress((void**)&Y,   g_Y);
    cudaGetSymbolAddress((void**)&X1,  g_X1);
    cudaGetSymbolAddress((void**)&HID, g_HID);
    cudaGetSymbolAddress((void**)&M,   g_M);

    dim3 gProj(DMODEL / 128, NTOK / 128);   // 8 x 64
    dim3 gFF1(DFFN / 128, NTOK / 128);      // 32 x 64

    // QKV projections
    gemm_tn_kernel<0><<<gProj, 256>>>(X, WQw, WQb, Q, NTOK, DMODEL, DMODEL);
    gemm_tn_kernel<0><<<gProj, 256>>>(X, WKw, WKb, K, NTOK, DMODEL, DMODEL);
    gemm_tn_kernel<0><<<gProj, 256>>>(X, WVw, WVb, V, NTOK, DMODEL, DMODEL);

    // attention
    size_t smem = 4 * 64 * TP * sizeof(float);   // ~69.6 KB
    cudaFuncSetAttribute(attn_kernel, cudaFuncAttributeMaxDynamicSharedMemorySize, (int)smem);
    attn_kernel<<<dim3(SLEN / 64, BATCH * NHEAD), 256, smem>>>(Q, K, V, CTX);

    // output projection + residual LN1
    gemm_tn_kernel<0><<<gProj, 256>>>(CTX, WOw, WOb, Y, NTOK, DMODEL, DMODEL);
    add_ln_kernel<<<NTOK, 256>>>(Y, X, ln1g, ln1b, X1);

    // MLP
    gemm_tn_kernel<1><<<gFF1, 256>>>(X1, W1, b1, HID, NTOK, DFFN, DMODEL);
    gemm_tn_kernel<0><<<gProj, 256>>>(HID, W2, b2, M, NTOK, DMODEL, DFFN);
    add_ln_kernel<<<NTOK, 256>>>(M, X1, ln2g, ln2b, out);
}

// round 3
// speedup vs baseline: 2.8284x; 2.8284x over previous
#include <cuda_runtime.h>
#include <cuda.h>
#include <cuda_bf16.h>
#include <cstdint>

#define SLEN 2048
#define BATCH 4
#define DMODEL 1024
#define NHEAD 16
#define DKH 64
#define DFFN 4096
#define NTOK (SLEN*BATCH)   // 8192
#define LN_EPS 1e-5f

// ---------------- scratch (device globals) ----------------------------------
__device__ __align__(1024) float g_Q[NTOK*DMODEL];
__device__ __align__(1024) float g_K[NTOK*DMODEL];
__device__ __align__(1024) float g_V[NTOK*DMODEL];
__device__ __align__(1024) float g_Y[NTOK*DMODEL];
__device__ __align__(1024) float g_X1[NTOK*DMODEL];
__device__ __align__(1024) float g_M[NTOK*DMODEL];

__device__ __align__(1024) __nv_bfloat16 g_Xhi[NTOK*DMODEL],  g_Xlo[NTOK*DMODEL];
__device__ __align__(1024) __nv_bfloat16 g_X1hi[NTOK*DMODEL], g_X1lo[NTOK*DMODEL];
__device__ __align__(1024) __nv_bfloat16 g_CTXhi[NTOK*DMODEL],g_CTXlo[NTOK*DMODEL];
__device__ __align__(1024) __nv_bfloat16 g_HIDhi[NTOK*DFFN],  g_HIDlo[NTOK*DFFN];
__device__ __align__(1024) __nv_bfloat16 g_WQhi[DMODEL*DMODEL], g_WQlo[DMODEL*DMODEL];
__device__ __align__(1024) __nv_bfloat16 g_WKhi[DMODEL*DMODEL], g_WKlo[DMODEL*DMODEL];
__device__ __align__(1024) __nv_bfloat16 g_WVhi[DMODEL*DMODEL], g_WVlo[DMODEL*DMODEL];
__device__ __align__(1024) __nv_bfloat16 g_WOhi[DMODEL*DMODEL], g_WOlo[DMODEL*DMODEL];
__device__ __align__(1024) __nv_bfloat16 g_W1hi[DFFN*DMODEL],   g_W1lo[DFFN*DMODEL];
__device__ __align__(1024) __nv_bfloat16 g_W2hi[DMODEL*DFFN],   g_W2lo[DMODEL*DFFN];

// ---------------- PTX helpers (base-ISA only: no tcgen05) --------------------
__device__ __forceinline__ uint32_t smem_to_u32(const void* p) {
    uint32_t a;
    asm("{ .reg .u64 t; cvta.to.shared.u64 t, %1; cvt.u32.u64 %0, t; }" : "=r"(a) : "l"(p));
    return a;
}
#define MBARRIER_INIT(mbar, cnt) \
    asm volatile("mbarrier.init.shared.b64 [%0], %1;" :: "r"((uint32_t)(mbar)), "r"((uint32_t)(cnt)) : "memory")
#define MBARRIER_EXPECT_TX(mbar, bytes) \
    asm volatile("mbarrier.arrive.expect_tx.shared.b64 _, [%0], %1;" :: "r"((uint32_t)(mbar)), "r"((uint32_t)(bytes)) : "memory")
#define FENCE_ASYNC_SHARED() asm volatile("fence.proxy.async.shared::cta;" ::: "memory")

#define MBARRIER_WAIT_PARITY(mbar_smem_addr, phase_parity) do { \
    uint32_t _mbar = (uint32_t)(mbar_smem_addr); \
    uint32_t _parity = (uint32_t)(phase_parity); \
    uint32_t _done; \
    asm volatile("{ .reg .pred p; mbarrier.try_wait.parity.acquire.cta.shared::cta.b64 p, [%1], %2; selp.b32 %0, 1, 0, p; }" \
        : "=r"(_done) : "r"(_mbar), "r"(_parity) : "memory"); \
    if (!_done) { \
        asm volatile("{ .reg .pred P1; WAIT_LOOP_%=: mbarrier.try_wait.parity.acquire.cta.shared::cta.b64 P1, [%0], %1, 0x989680; @P1 bra.uni WAIT_DONE_%=; bra.uni WAIT_LOOP_%=; WAIT_DONE_%=: }" \
            :: "r"(_mbar), "r"(_parity) : "memory"); \
    } \
} while(0)

__device__ __forceinline__ void tma_load_2d(uint32_t dst_smem, const CUtensorMap* m,
                                            int x, int y, uint32_t mbar) {
    asm volatile(
        "cp.async.bulk.tensor.2d.shared::cta.global.tile.mbarrier::complete_tx::bytes "
        "[%0], [%1, {%2, %3}], [%4];"
        :: "r"(dst_smem), "l"(m), "r"(x), "r"(y), "r"(mbar) : "memory");
}

// mma.sync m16n8k16 bf16 (base sm_80 ISA — compiles for compute_103)
__device__ __forceinline__ void mma_bf16(float* d, const uint32_t* a, const uint32_t* b) {
    asm volatile(
        "mma.sync.aligned.m16n8k16.row.col.f32.bf16.bf16.f32 "
        "{%0,%1,%2,%3},{%4,%5,%6,%7},{%8,%9},{%0,%1,%2,%3};"
        : "+f"(d[0]), "+f"(d[1]), "+f"(d[2]), "+f"(d[3])
        : "r"(a[0]), "r"(a[1]), "r"(a[2]), "r"(a[3]), "r"(b[0]), "r"(b[1]));
}

// ---------------- fp32 -> bf16 hi/lo split -----------------------------------
__device__ __forceinline__ void split_one(float v, __nv_bfloat16& h, __nv_bfloat16& l) {
    h = __float2bfloat16_rn(v);
    l = __float2bfloat16_rn(v - __bfloat162float(h));
}

__global__ void __launch_bounds__(256) cvt_kernel(
    const float* __restrict__ x, __nv_bfloat16* __restrict__ hi,
    __nv_bfloat16* __restrict__ lo, int n4)
{
    int i = blockIdx.x * blockDim.x + threadIdx.x;
    if (i >= n4) return;
    float4 v = ((const float4*)x)[i];
    __nv_bfloat16 h0,h1,h2,h3,l0,l1,l2,l3;
    split_one(v.x,h0,l0); split_one(v.y,h1,l1);
    split_one(v.z,h2,l2); split_one(v.w,h3,l3);
    __nv_bfloat162 ph0 = {h0,h1}, ph1 = {h2,h3};
    __nv_bfloat162 pl0 = {l0,l1}, pl1 = {l2,l3};
    uint2 uh, ul;
    uh.x = *(uint32_t*)&ph0; uh.y = *(uint32_t*)&ph1;
    ul.x = *(uint32_t*)&pl0; ul.y = *(uint32_t*)&pl1;
    ((uint2*)hi)[i] = uh;
    ((uint2*)lo)[i] = ul;
}

// ---------------- split-bf16 GEMM via mma.sync + TMA double buffer -----------
// C[M,N] = A[M,K] @ Bw[N,K]^T + bias.  Tiles 128x128x64, 8 warps (4m x 2n).
// smem stage (64KB): Ahi(16K) Alo(16K) Bhi(16K) Blo(16K), SW128 swizzled 128B rows.
#define STAGE_BYTES 65536
#define T_AHI 0
#define T_ALO 16384
#define T_BHI 32768
#define T_BLO 49152
#define GEMM_SMEM (2*STAGE_BYTES + 32)

__device__ __forceinline__ uint32_t swoff(int row, int colb) {
    return (uint32_t)(row * 128 + (colb ^ ((row & 7) * 16)));
}

template<int WRITE_F32, int WRITE_HILO, int RELU>
__global__ void __launch_bounds__(256, 1) gemm_mma_kernel(
    const __grid_constant__ CUtensorMap mAhi,
    const __grid_constant__ CUtensorMap mAlo,
    const __grid_constant__ CUtensorMap mBhi,
    const __grid_constant__ CUtensorMap mBlo,
    const float* __restrict__ bias,
    float* __restrict__ C, __nv_bfloat16* __restrict__ Chi, __nv_bfloat16* __restrict__ Clo,
    int M, int N, int K)
{
    extern __shared__ char smem[];
    const uint32_t sbase = smem_to_u32(smem);
    const uint32_t mb0 = sbase + 2 * STAGE_BYTES;       // full barrier buf0
    const uint32_t mb1 = mb0 + 8;                       // full barrier buf1
    const int tid = threadIdx.x;
    const int wid = tid >> 5;
    const int lane = tid & 31;
    const int g = lane >> 2;       // group row 0..7
    const int tq = lane & 3;       // quad col 0..3
    const int wm = wid & 3;        // warp m 0..3 (32 rows each)
    const int wn = wid >> 2;       // warp n 0..1 (64 cols each)
    const int bm = blockIdx.y * 128;
    const int bn = blockIdx.x * 128;
    const int nst = K >> 6;

    if (tid == 0) {
        MBARRIER_INIT(mb0, 1);
        MBARRIER_INIT(mb1, 1);
    }
    FENCE_ASYNC_SHARED();
    __syncthreads();

    if (tid == 0) {
#pragma unroll
        for (int s = 0; s < 2; s++) {
            uint32_t mb = (s == 0) ? mb0 : mb1;
            uint32_t dst = sbase + s * STAGE_BYTES;
            MBARRIER_EXPECT_TX(mb, STAGE_BYTES);
            tma_load_2d(dst + T_AHI, &mAhi, s * 64, bm, mb);
            tma_load_2d(dst + T_ALO, &mAlo, s * 64, bm, mb);
            tma_load_2d(dst + T_BHI, &mBhi, s * 64, bn, mb);
            tma_load_2d(dst + T_BLO, &mBlo, s * 64, bn, mb);
        }
    }

    float acc[2][8][4];
#pragma unroll
    for (int t = 0; t < 2; t++)
#pragma unroll
        for (int j = 0; j < 8; j++)
#pragma unroll
            for (int q = 0; q < 4; q++) acc[t][j][q] = 0.f;

    const int arow0 = wm * 32 + g;
    const int brow0 = wn * 64 + g;

    for (int s = 0; s < nst; s++) {
        MBARRIER_WAIT_PARITY((s & 1) ? mb1 : mb0, (s >> 1) & 1);
        const char* buf = smem + (s & 1) * STAGE_BYTES;

#pragma unroll
        for (int ks = 0; ks < 4; ks++) {
            const int c0 = ks * 32 + tq * 4;
            const int c1 = c0 + 16;
            uint32_t ah[2][4], al[2][4];
#pragma unroll
            for (int t = 0; t < 2; t++) {
                int r0 = arow0 + t * 16, r1 = r0 + 8;
                ah[t][0] = *(const uint32_t*)(buf + T_AHI + swoff(r0, c0));
                ah[t][1] = *(const uint32_t*)(buf + T_AHI + swoff(r1, c0));
                ah[t][2] = *(const uint32_t*)(buf + T_AHI + swoff(r0, c1));
                ah[t][3] = *(const uint32_t*)(buf + T_AHI + swoff(r1, c1));
                al[t][0] = *(const uint32_t*)(buf + T_ALO + swoff(r0, c0));
                al[t][1] = *(const uint32_t*)(buf + T_ALO + swoff(r1, c0));
                al[t][2] = *(const uint32_t*)(buf + T_ALO + swoff(r0, c1));
                al[t][3] = *(const uint32_t*)(buf + T_ALO + swoff(r1, c1));
            }
            uint32_t bh[8][2], bl[8][2];
#pragma unroll
            for (int j = 0; j < 8; j++) {
                int rn = brow0 + j * 8;
                bh[j][0] = *(const uint32_t*)(buf + T_BHI + swoff(rn, c0));
                bh[j][1] = *(const uint32_t*)(buf + T_BHI + swoff(rn, c1));
                bl[j][0] = *(const uint32_t*)(buf + T_BLO + swoff(rn, c0));
                bl[j][1] = *(const uint32_t*)(buf + T_BLO + swoff(rn, c1));
            }
#pragma unroll
            for (int t = 0; t < 2; t++)
#pragma unroll
                for (int j = 0; j < 8; j++) {
                    mma_bf16(acc[t][j], ah[t], bh[j]);
                    mma_bf16(acc[t][j], ah[t], bl[j]);
                    mma_bf16(acc[t][j], al[t], bh[j]);
                }
        }

        __syncthreads();   // all warps done reading buf (s&1)
        if (tid == 0 && s + 2 < nst) {
            uint32_t mb = (s & 1) ? mb1 : mb0;
            uint32_t dst = sbase + (s & 1) * STAGE_BYTES;
            MBARRIER_EXPECT_TX(mb, STAGE_BYTES);
            tma_load_2d(dst + T_AHI, &mAhi, (s + 2) * 64, bm, mb);
            tma_load_2d(dst + T_ALO, &mAlo, (s + 2) * 64, bm, mb);
            tma_load_2d(dst + T_BHI, &mBhi, (s + 2) * 64, bn, mb);
            tma_load_2d(dst + T_BLO, &mBlo, (s + 2) * 64, bn, mb);
        }
    }

    // ---- epilogue ----
#pragma unroll
    for (int t = 0; t < 2; t++) {
        int row = bm + wm * 32 + t * 16 + g;
#pragma unroll
        for (int j = 0; j < 8; j++) {
            int col = bn + wn * 64 + j * 8 + tq * 2;
            float2 bj = *(const float2*)&bias[col];
            float v0 = acc[t][j][0] + bj.x;
            float v1 = acc[t][j][1] + bj.y;
            float v2 = acc[t][j][2] + bj.x;
            float v3 = acc[t][j][3] + bj.y;
            if (RELU) {
                v0 = fmaxf(v0, 0.f); v1 = fmaxf(v1, 0.f);
                v2 = fmaxf(v2, 0.f); v3 = fmaxf(v3, 0.f);
            }
            if (WRITE_F32) {
                *(float2*)&C[(size_t)row * N + col]       = make_float2(v0, v1);
                *(float2*)&C[(size_t)(row + 8) * N + col] = make_float2(v2, v3);
            }
            if (WRITE_HILO) {
                __nv_bfloat16 h0,h1,h2,h3,l0,l1,l2,l3;
                split_one(v0, h0, l0); split_one(v1, h1, l1);
                split_one(v2, h2, l2); split_one(v3, h3, l3);
                __nv_bfloat162 ph0 = {h0,h1}, ph1 = {h2,h3};
                __nv_bfloat162 pl0 = {l0,l1}, pl1 = {l2,l3};
                *(uint32_t*)&Chi[(size_t)row * N + col]       = *(uint32_t*)&ph0;
                *(uint32_t*)&Chi[(size_t)(row + 8) * N + col] = *(uint32_t*)&ph1;
                *(uint32_t*)&Clo[(size_t)row * N + col]       = *(uint32_t*)&pl0;
                *(uint32_t*)&Clo[(size_t)(row + 8) * N + col] = *(uint32_t*)&pl1;
            }
        }
    }
}

// ---------------- Flash attention (fp32, writes bf16 hi/lo ctx) --------------
#define TP 68
__global__ void __launch_bounds__(256) attn_kernel(
    const float* __restrict__ Qg, const float* __restrict__ Kg,
    const float* __restrict__ Vg,
    __nv_bfloat16* __restrict__ Ohi, __nv_bfloat16* __restrict__ Olo)
{
    extern __shared__ float sm[];
    float* Qs = sm;
    float* Ks = Qs + 64 * TP;
    float* Vs = Ks + 64 * TP;
    float* Ps = Vs + 64 * TP;

    const int tid = threadIdx.x;
    const int q0 = blockIdx.x * 64;
    const int b = blockIdx.y / NHEAD;
    const int h = blockIdx.y % NHEAD;
    const int lr = tid >> 2;
    const int lc = (tid & 3) * 16;
    const int tx = tid & 15;
    const int ty = tid >> 4;
    const int headoff = h * DKH;

    {
        const float* qp = Qg + ((size_t)(q0 + lr) * BATCH + b) * DMODEL + headoff + lc;
#pragma unroll
        for (int i = 0; i < 16; i += 4) {
            float4 v = *(const float4*)(qp + i);
            Qs[(lc + i + 0) * TP + lr] = v.x * 0.125f;
            Qs[(lc + i + 1) * TP + lr] = v.y * 0.125f;
            Qs[(lc + i + 2) * TP + lr] = v.z * 0.125f;
            Qs[(lc + i + 3) * TP + lr] = v.w * 0.125f;
        }
    }

    float m_i[4], l_i[4], acc[4][4];
#pragma unroll
    for (int r = 0; r < 4; r++) {
        m_i[r] = -1e30f; l_i[r] = 0.f;
#pragma unroll
        for (int c = 0; c < 4; c++) acc[r][c] = 0.f;
    }

    for (int kt = 0; kt < SLEN / 64; kt++) {
        __syncthreads();
        {
            const float* kp = Kg + ((size_t)(kt * 64 + lr) * BATCH + b) * DMODEL + headoff + lc;
            const float* vp = Vg + ((size_t)(kt * 64 + lr) * BATCH + b) * DMODEL + headoff + lc;
#pragma unroll
            for (int i = 0; i < 16; i += 4) {
                float4 v = *(const float4*)(kp + i);
                Ks[(lc + i + 0) * TP + lr] = v.x;
                Ks[(lc + i + 1) * TP + lr] = v.y;
                Ks[(lc + i + 2) * TP + lr] = v.z;
                Ks[(lc + i + 3) * TP + lr] = v.w;
                float4 w = *(const float4*)(vp + i);
                *(float4*)&Vs[lr * TP + lc + i] = w;
            }
        }
        __syncthreads();

        float sc[4][4];
#pragma unroll
        for (int r = 0; r < 4; r++)
#pragma unroll
            for (int c = 0; c < 4; c++) sc[r][c] = 0.f;

#pragma unroll 8
        for (int k = 0; k < 64; k++) {
            float4 qa = *(const float4*)&Qs[k * TP + ty * 4];
            float4 kb = *(const float4*)&Ks[k * TP + tx * 4];
            float qr[4] = {qa.x, qa.y, qa.z, qa.w};
            float kr[4] = {kb.x, kb.y, kb.z, kb.w};
#pragma unroll
            for (int r = 0; r < 4; r++)
#pragma unroll
                for (int c = 0; c < 4; c++)
                    sc[r][c] = fmaf(qr[r], kr[c], sc[r][c]);
        }

        float p[4][4];
#pragma unroll
        for (int r = 0; r < 4; r++) {
            float mloc = fmaxf(fmaxf(sc[r][0], sc[r][1]), fmaxf(sc[r][2], sc[r][3]));
#pragma unroll
            for (int off = 8; off >= 1; off >>= 1)
                mloc = fmaxf(mloc, __shfl_xor_sync(0xffffffffu, mloc, off));
            float mnew = fmaxf(m_i[r], mloc);
            float alpha = __expf(m_i[r] - mnew);
            m_i[r] = mnew;
            float ls = 0.f;
#pragma unroll
            for (int c = 0; c < 4; c++) {
                p[r][c] = __expf(sc[r][c] - mnew);
                ls += p[r][c];
            }
#pragma unroll
            for (int off = 8; off >= 1; off >>= 1)
                ls += __shfl_xor_sync(0xffffffffu, ls, off);
            l_i[r] = l_i[r] * alpha + ls;
#pragma unroll
            for (int c = 0; c < 4; c++) acc[r][c] *= alpha;
        }

#pragma unroll
        for (int r = 0; r < 4; r++) {
            float4 pv = make_float4(p[r][0], p[r][1], p[r][2], p[r][3]);
            *(float4*)&Ps[(ty * 4 + r) * TP + tx * 4] = pv;
        }
        __syncthreads();

#pragma unroll 8
        for (int k = 0; k < 64; k++) {
            float4 vb = *(const float4*)&Vs[k * TP + tx * 4];
            float vr[4] = {vb.x, vb.y, vb.z, vb.w};
#pragma unroll
            for (int r = 0; r < 4; r++) {
                float pa = Ps[(ty * 4 + r) * TP + k];
#pragma unroll
                for (int c = 0; c < 4; c++)
                    acc[r][c] = fmaf(pa, vr[c], acc[r][c]);
            }
        }
    }

#pragma unroll
    for (int r = 0; r < 4; r++) {
        float inv = 1.0f / l_i[r];
        int m = ty * 4 + r;
        size_t off = ((size_t)(q0 + m) * BATCH + b) * DMODEL + headoff + tx * 4;
        __nv_bfloat16 h0,h1,h2,h3,l0,l1,l2,l3;
        split_one(acc[r][0] * inv, h0, l0);
        split_one(acc[r][1] * inv, h1, l1);
        split_one(acc[r][2] * inv, h2, l2);
        split_one(acc[r][3] * inv, h3, l3);
        __nv_bfloat162 ph0 = {h0,h1}, ph1 = {h2,h3};
        __nv_bfloat162 pl0 = {l0,l1}, pl1 = {l2,l3};
        uint2 uh, ul;
        uh.x = *(uint32_t*)&ph0; uh.y = *(uint32_t*)&ph1;
        ul.x = *(uint32_t*)&pl0; ul.y = *(uint32_t*)&pl1;
        *(uint2*)(Ohi + off) = uh;
        *(uint2*)(Olo + off) = ul;
    }
}

// ---------------- fused residual add + LayerNorm -----------------------------
template<int HILO>
__global__ void __launch_bounds__(256) add_ln_kernel(
    const float* __restrict__ A, const float* __restrict__ R,
    const float* __restrict__ gam, const float* __restrict__ bet,
    float* __restrict__ out, __nv_bfloat16* __restrict__ Ohi,
    __nv_bfloat16* __restrict__ Olo)
{
    __shared__ float red_s[8];
    __shared__ float red_ss[8];
    __shared__ float s_mu, s_rstd;
    const int row = blockIdx.x;
    const int t = threadIdx.x;
    const float4* a4 = (const float4*)(A + (size_t)row * DMODEL);
    const float4* r4 = (const float4*)(R + (size_t)row * DMODEL);
    float4 v = a4[t];
    float4 w = r4[t];
    v.x += w.x; v.y += w.y; v.z += w.z; v.w += w.w;
    float s = v.x + v.y + v.z + v.w;
    float ss = v.x * v.x + v.y * v.y + v.z * v.z + v.w * v.w;
#pragma unroll
    for (int off = 16; off >= 1; off >>= 1) {
        s  += __shfl_xor_sync(0xffffffffu, s, off);
        ss += __shfl_xor_sync(0xffffffffu, ss, off);
    }
    if ((t & 31) == 0) { red_s[t >> 5] = s; red_ss[t >> 5] = ss; }
    __syncthreads();
    if (t == 0) {
        float ts = 0.f, tss = 0.f;
#pragma unroll
        for (int i = 0; i < 8; i++) { ts += red_s[i]; tss += red_ss[i]; }
        float mu = ts * (1.0f / DMODEL);
        float var = tss * (1.0f / DMODEL) - mu * mu;
        s_mu = mu;
        s_rstd = rsqrtf(var + LN_EPS);
    }
    __syncthreads();
    float mu = s_mu, rs = s_rstd;
    float4 g = ((const float4*)gam)[t], bb = ((const float4*)bet)[t];
    float4 o;
    o.x = (v.x - mu) * rs * g.x + bb.x;
    o.y = (v.y - mu) * rs * g.y + bb.y;
    o.z = (v.z - mu) * rs * g.z + bb.z;
    o.w = (v.w - mu) * rs * g.w + bb.w;
    ((float4*)(out + (size_t)row * DMODEL))[t] = o;
    if (HILO) {
        __nv_bfloat16 h0,h1,h2,h3,l0,l1,l2,l3;
        split_one(o.x, h0, l0); split_one(o.y, h1, l1);
        split_one(o.z, h2, l2); split_one(o.w, h3, l3);
        __nv_bfloat162 ph0 = {h0,h1}, ph1 = {h2,h3};
        __nv_bfloat162 pl0 = {l0,l1}, pl1 = {l2,l3};
        uint2 uh, ul;
        uh.x = *(uint32_t*)&ph0; uh.y = *(uint32_t*)&ph1;
        ul.x = *(uint32_t*)&pl0; ul.y = *(uint32_t*)&pl1;
        ((uint2*)(Ohi + (size_t)row * DMODEL))[t] = uh;
        ((uint2*)(Olo + (size_t)row * DMODEL))[t] = ul;
    }
}

// ---------------- host: tensormap + launch ------------------------------------
typedef CUresult (*EncodeFn)(
    CUtensorMap*, CUtensorMapDataType, cuuint32_t, void*,
    const cuuint64_t*, const cuuint64_t*, const cuuint32_t*, const cuuint32_t*,
    CUtensorMapInterleave, CUtensorMapSwizzle, CUtensorMapL2promotion,
    CUtensorMapFloatOOBfill);

static void make_desc(EncodeFn enc, CUtensorMap* out, void* ptr,
                      uint64_t rows, uint64_t K)
{
    cuuint64_t dims[2]    = {K, rows};
    cuuint64_t strides[1] = {K * 2};
    cuuint32_t box[2]     = {64, 128};
    cuuint32_t estr[2]    = {1, 1};
    enc(out, CU_TENSOR_MAP_DATA_TYPE_BFLOAT16, 2, ptr, dims, strides, box, estr,
        CU_TENSOR_MAP_INTERLEAVE_NONE, CU_TENSOR_MAP_SWIZZLE_128B,
        CU_TENSOR_MAP_L2_PROMOTION_L2_128B, CU_TENSOR_MAP_FLOAT_OOB_FILL_NONE);
}

extern "C" void kernel_launch(void* const* d_in, const int* in_sizes, int n_in,
                              void* d_out, int out_size)
{
    const float* X    = (const float*)d_in[0];
    const float* WQw  = (const float*)d_in[1];
    const float* WQb  = (const float*)d_in[2];
    const float* WKw  = (const float*)d_in[3];
    const float* WKb  = (const float*)d_in[4];
    const float* WVw  = (const float*)d_in[5];
    const float* WVb  = (const float*)d_in[6];
    const float* WOw  = (const float*)d_in[7];
    const float* WOb  = (const float*)d_in[8];
    const float* ln1g = (const float*)d_in[9];
    const float* ln1b = (const float*)d_in[10];
    const float* W1   = (const float*)d_in[11];
    const float* b1   = (const float*)d_in[12];
    const float* W2   = (const float*)d_in[13];
    const float* b2   = (const float*)d_in[14];
    const float* ln2g = (const float*)d_in[15];
    const float* ln2b = (const float*)d_in[16];
    float* out = (float*)d_out;

    float *Q, *K, *V, *Y, *X1, *M;
    cudaGetSymbolAddress((void**)&Q,  g_Q);
    cudaGetSymbolAddress((void**)&K,  g_K);
    cudaGetSymbolAddress((void**)&V,  g_V);
    cudaGetSymbolAddress((void**)&Y,  g_Y);
    cudaGetSymbolAddress((void**)&X1, g_X1);
    cudaGetSymbolAddress((void**)&M,  g_M);

    __nv_bfloat16 *Xhi,*Xlo,*X1hi,*X1lo,*CTXhi,*CTXlo,*HIDhi,*HIDlo;
    __nv_bfloat16 *WQhi,*WQlo,*WKhi,*WKlo,*WVhi,*WVlo,*WOhi,*WOlo,*W1hi,*W1lo,*W2hi,*W2lo;
    cudaGetSymbolAddress((void**)&Xhi,  g_Xhi);  cudaGetSymbolAddress((void**)&Xlo,  g_Xlo);
    cudaGetSymbolAddress((void**)&X1hi, g_X1hi); cudaGetSymbolAddress((void**)&X1lo, g_X1lo);
    cudaGetSymbolAddress((void**)&CTXhi,g_CTXhi);cudaGetSymbolAddress((void**)&CTXlo,g_CTXlo);
    cudaGetSymbolAddress((void**)&HIDhi,g_HIDhi);cudaGetSymbolAddress((void**)&HIDlo,g_HIDlo);
    cudaGetSymbolAddress((void**)&WQhi, g_WQhi); cudaGetSymbolAddress((void**)&WQlo, g_WQlo);
    cudaGetSymbolAddress((void**)&WKhi, g_WKhi); cudaGetSymbolAddress((void**)&WKlo, g_WKlo);
    cudaGetSymbolAddress((void**)&WVhi, g_WVhi); cudaGetSymbolAddress((void**)&WVlo, g_WVlo);
    cudaGetSymbolAddress((void**)&WOhi, g_WOhi); cudaGetSymbolAddress((void**)&WOlo, g_WOlo);
    cudaGetSymbolAddress((void**)&W1hi, g_W1hi); cudaGetSymbolAddress((void**)&W1lo, g_W1lo);
    cudaGetSymbolAddress((void**)&W2hi, g_W2hi); cudaGetSymbolAddress((void**)&W2lo, g_W2lo);

    // driver entry point for tensormap encode (cudart-only link)
    EncodeFn enc = nullptr;
    {
        void* fp = nullptr;
        cudaDriverEntryPointQueryResult qr;
        cudaGetDriverEntryPoint("cuTensorMapEncodeTiled", &fp,
                                cudaEnableDefault, &qr);
        enc = (EncodeFn)fp;
    }

    // descriptors
    CUtensorMap dXhi, dXlo, dWQhi, dWQlo, dWKhi, dWKlo, dWVhi, dWVlo;
    CUtensorMap dCTXhi, dCTXlo, dWOhi, dWOlo;
    CUtensorMap dX1hi, dX1lo, dW1hi, dW1lo, dHIDhi, dHIDlo, dW2hi, dW2lo;
    make_desc(enc, &dXhi,  Xhi,  NTOK, DMODEL);  make_desc(enc, &dXlo,  Xlo,  NTOK, DMODEL);
    make_desc(enc, &dWQhi, WQhi, DMODEL, DMODEL);make_desc(enc, &dWQlo, WQlo, DMODEL, DMODEL);
    make_desc(enc, &dWKhi, WKhi, DMODEL, DMODEL);make_desc(enc, &dWKlo, WKlo, DMODEL, DMODEL);
    make_desc(enc, &dWVhi, WVhi, DMODEL, DMODEL);make_desc(enc, &dWVlo, WVlo, DMODEL, DMODEL);
    make_desc(enc, &dCTXhi,CTXhi,NTOK, DMODEL);  make_desc(enc, &dCTXlo,CTXlo,NTOK, DMODEL);
    make_desc(enc, &dWOhi, WOhi, DMODEL, DMODEL);make_desc(enc, &dWOlo, WOlo, DMODEL, DMODEL);
    make_desc(enc, &dX1hi, X1hi, NTOK, DMODEL);  make_desc(enc, &dX1lo, X1lo, NTOK, DMODEL);
    make_desc(enc, &dW1hi, W1hi, DFFN, DMODEL);  make_desc(enc, &dW1lo, W1lo, DFFN, DMODEL);
    make_desc(enc, &dHIDhi,HIDhi,NTOK, DFFN);    make_desc(enc, &dHIDlo,HIDlo,NTOK, DFFN);
    make_desc(enc, &dW2hi, W2hi, DMODEL, DFFN);  make_desc(enc, &dW2lo, W2lo, DMODEL, DFFN);

    cudaFuncSetAttribute(gemm_mma_kernel<1,0,0>, cudaFuncAttributeMaxDynamicSharedMemorySize, GEMM_SMEM);
    cudaFuncSetAttribute(gemm_mma_kernel<0,1,1>, cudaFuncAttributeMaxDynamicSharedMemorySize, GEMM_SMEM);
    size_t asmem = 4 * 64 * TP * sizeof(float);
    cudaFuncSetAttribute(attn_kernel, cudaFuncAttributeMaxDynamicSharedMemorySize, (int)asmem);

    // ---- fp32 -> bf16 hi/lo splits ----
    cvt_kernel<<<(NTOK*DMODEL/4 + 255)/256, 256>>>(X,   Xhi,  Xlo,  NTOK*DMODEL/4);
    cvt_kernel<<<(DMODEL*DMODEL/4 + 255)/256, 256>>>(WQw, WQhi, WQlo, DMODEL*DMODEL/4);
    cvt_kernel<<<(DMODEL*DMODEL/4 + 255)/256, 256>>>(WKw, WKhi, WKlo, DMODEL*DMODEL/4);
    cvt_kernel<<<(DMODEL*DMODEL/4 + 255)/256, 256>>>(WVw, WVhi, WVlo, DMODEL*DMODEL/4);
    cvt_kernel<<<(DMODEL*DMODEL/4 + 255)/256, 256>>>(WOw, WOhi, WOlo, DMODEL*DMODEL/4);
    cvt_kernel<<<(DFFN*DMODEL/4 + 255)/256, 256>>>(W1,  W1hi, W1lo, DFFN*DMODEL/4);
    cvt_kernel<<<(DMODEL*DFFN/4 + 255)/256, 256>>>(W2,  W2hi, W2lo, DMODEL*DFFN/4);

    dim3 gProj(DMODEL / 128, NTOK / 128);   // 8 x 64
    dim3 gFF1(DFFN / 128, NTOK / 128);      // 32 x 64

    // ---- QKV projections ----
    gemm_mma_kernel<1,0,0><<<gProj, 256, GEMM_SMEM>>>(dXhi, dXlo, dWQhi, dWQlo, WQb, Q, nullptr, nullptr, NTOK, DMODEL, DMODEL);
    gemm_mma_kernel<1,0,0><<<gProj, 256, GEMM_SMEM>>>(dXhi, dXlo, dWKhi, dWKlo, WKb, K, nullptr, nullptr, NTOK, DMODEL, DMODEL);
    gemm_mma_kernel<1,0,0><<<gProj, 256, GEMM_SMEM>>>(dXhi, dXlo, dWVhi, dWVlo, WVb, V, nullptr, nullptr, NTOK, DMODEL, DMODEL);

    // ---- attention (fp32 CUDA-core, emits hi/lo ctx) ----
    attn_kernel<<<dim3(SLEN / 64, BATCH * NHEAD), 256, asmem>>>(Q, K, V, CTXhi, CTXlo);

    // ---- output projection + residual LN1 ----
    gemm_mma_kernel<1,0,0><<<gProj, 256, GEMM_SMEM>>>(dCTXhi, dCTXlo, dWOhi, dWOlo, WOb, Y, nullptr, nullptr, NTOK, DMODEL, DMODEL);
    add_ln_kernel<1><<<NTOK, 256>>>(Y, X, ln1g, ln1b, X1, X1hi, X1lo);

    // ---- MLP ----
    gemm_mma_kernel<0,1,1><<<gFF1, 256, GEMM_SMEM>>>(dX1hi, dX1lo, dW1hi, dW1lo, b1, nullptr, HIDhi, HIDlo, NTOK, DFFN, DMODEL);
    gemm_mma_kernel<1,0,0><<<gProj, 256, GEMM_SMEM>>>(dHIDhi, dHIDlo, dW2hi, dW2lo, b2, M, nullptr, nullptr, NTOK, DMODEL, DFFN);
    add_ln_kernel<0><<<NTOK, 256>>>(M, X1, ln2g, ln2b, out, nullptr, nullptr);
}

// round 4
// speedup vs baseline: 4.9117x; 1.7365x over previous
#include <cuda_runtime.h>
#include <cuda.h>
#include <cuda_bf16.h>
#include <cstdint>

#define SLEN 2048
#define BATCH 4
#define DMODEL 1024
#define NHEAD 16
#define DKH 64
#define DFFN 4096
#define NTOK (SLEN*BATCH)   // 8192
#define LN_EPS 1e-5f

// ---------------- scratch (device globals) ----------------------------------
__device__ __align__(1024) float g_Y[NTOK*DMODEL];
__device__ __align__(1024) float g_X1[NTOK*DMODEL];
__device__ __align__(1024) float g_M[NTOK*DMODEL];

__device__ __align__(1024) __nv_bfloat16 g_Xhi[NTOK*DMODEL],  g_Xlo[NTOK*DMODEL];
__device__ __align__(1024) __nv_bfloat16 g_X1hi[NTOK*DMODEL], g_X1lo[NTOK*DMODEL];
__device__ __align__(1024) __nv_bfloat16 g_CTXhi[NTOK*DMODEL],g_CTXlo[NTOK*DMODEL];
__device__ __align__(1024) __nv_bfloat16 g_Qhi[NTOK*DMODEL],  g_Qlo[NTOK*DMODEL];
__device__ __align__(1024) __nv_bfloat16 g_Khi[NTOK*DMODEL],  g_Klo[NTOK*DMODEL];
__device__ __align__(1024) __nv_bfloat16 g_Vhi[NTOK*DMODEL],  g_Vlo[NTOK*DMODEL];
__device__ __align__(1024) __nv_bfloat16 g_VThi[NTOK*DMODEL], g_VTlo[NTOK*DMODEL];
__device__ __align__(1024) __nv_bfloat16 g_HIDhi[NTOK*DFFN],  g_HIDlo[NTOK*DFFN];
__device__ __align__(1024) __nv_bfloat16 g_WQhi[DMODEL*DMODEL], g_WQlo[DMODEL*DMODEL];
__device__ __align__(1024) __nv_bfloat16 g_WKhi[DMODEL*DMODEL], g_WKlo[DMODEL*DMODEL];
__device__ __align__(1024) __nv_bfloat16 g_WVhi[DMODEL*DMODEL], g_WVlo[DMODEL*DMODEL];
__device__ __align__(1024) __nv_bfloat16 g_WOhi[DMODEL*DMODEL], g_WOlo[DMODEL*DMODEL];
__device__ __align__(1024) __nv_bfloat16 g_W1hi[DFFN*DMODEL],   g_W1lo[DFFN*DMODEL];
__device__ __align__(1024) __nv_bfloat16 g_W2hi[DMODEL*DFFN],   g_W2lo[DMODEL*DFFN];

// ---------------- PTX helpers (base-ISA only) --------------------------------
__device__ __forceinline__ uint32_t smem_to_u32(const void* p) {
    uint32_t a;
    asm("{ .reg .u64 t; cvta.to.shared.u64 t, %1; cvt.u32.u64 %0, t; }" : "=r"(a) : "l"(p));
    return a;
}
#define MBARRIER_INIT(mbar, cnt) \
    asm volatile("mbarrier.init.shared.b64 [%0], %1;" :: "r"((uint32_t)(mbar)), "r"((uint32_t)(cnt)) : "memory")
#define MBARRIER_EXPECT_TX(mbar, bytes) \
    asm volatile("mbarrier.arrive.expect_tx.shared.b64 _, [%0], %1;" :: "r"((uint32_t)(mbar)), "r"((uint32_t)(bytes)) : "memory")
#define FENCE_ASYNC_SHARED() asm volatile("fence.proxy.async.shared::cta;" ::: "memory")

#define MBARRIER_WAIT_PARITY(mbar_smem_addr, phase_parity) do { \
    uint32_t _mbar = (uint32_t)(mbar_smem_addr); \
    uint32_t _parity = (uint32_t)(phase_parity); \
    uint32_t _done; \
    asm volatile("{ .reg .pred p; mbarrier.try_wait.parity.acquire.cta.shared::cta.b64 p, [%1], %2; selp.b32 %0, 1, 0, p; }" \
        : "=r"(_done) : "r"(_mbar), "r"(_parity) : "memory"); \
    if (!_done) { \
        asm volatile("{ .reg .pred P1; WAIT_LOOP_%=: mbarrier.try_wait.parity.acquire.cta.shared::cta.b64 P1, [%0], %1, 0x989680; @P1 bra.uni WAIT_DONE_%=; bra.uni WAIT_LOOP_%=; WAIT_DONE_%=: }" \
            :: "r"(_mbar), "r"(_parity) : "memory"); \
    } \
} while(0)

__device__ __forceinline__ void tma_load_2d(uint32_t dst_smem, const CUtensorMap* m,
                                            int x, int y, uint32_t mbar) {
    asm volatile(
        "cp.async.bulk.tensor.2d.shared::cta.global.tile.mbarrier::complete_tx::bytes "
        "[%0], [%1, {%2, %3}], [%4];"
        :: "r"(dst_smem), "l"(m), "r"(x), "r"(y), "r"(mbar) : "memory");
}

__device__ __forceinline__ void mma_bf16(float* d, const uint32_t* a, const uint32_t* b) {
    asm volatile(
        "mma.sync.aligned.m16n8k16.row.col.f32.bf16.bf16.f32 "
        "{%0,%1,%2,%3},{%4,%5,%6,%7},{%8,%9},{%0,%1,%2,%3};"
        : "+f"(d[0]), "+f"(d[1]), "+f"(d[2]), "+f"(d[3])
        : "r"(a[0]), "r"(a[1]), "r"(a[2]), "r"(a[3]), "r"(b[0]), "r"(b[1]));
}

__device__ __forceinline__ void split_one(float v, __nv_bfloat16& h, __nv_bfloat16& l) {
    h = __float2bfloat16_rn(v);
    l = __float2bfloat16_rn(v - __bfloat162float(h));
}
__device__ __forceinline__ void split_pack2(float a, float b, uint32_t& hi, uint32_t& lo) {
    __nv_bfloat16 ha, hb, la, lb;
    split_one(a, ha, la); split_one(b, hb, lb);
    __nv_bfloat162 ph = {ha, hb}, pl = {la, lb};
    hi = *(uint32_t*)&ph; lo = *(uint32_t*)&pl;
}

__device__ __forceinline__ uint32_t swoff(int row, int colb) {
    return (uint32_t)(row * 128 + (colb ^ ((row & 7) * 16)));
}

// ---------------- fp32 -> bf16 hi/lo split ------------------------------------
__global__ void __launch_bounds__(256) cvt_kernel(
    const float* __restrict__ x, __nv_bfloat16* __restrict__ hi,
    __nv_bfloat16* __restrict__ lo, int n4)
{
    int i = blockIdx.x * blockDim.x + threadIdx.x;
    if (i >= n4) return;
    float4 v = ((const float4*)x)[i];
    uint2 uh, ul;
    split_pack2(v.x, v.y, uh.x, ul.x);
    split_pack2(v.z, v.w, uh.y, ul.y);
    ((uint2*)hi)[i] = uh;
    ((uint2*)lo)[i] = ul;
}

// ---------------- split-bf16 GEMM (TMA + mma.sync, from R3) -------------------
#define STAGE_BYTES 65536
#define T_AHI 0
#define T_ALO 16384
#define T_BHI 32768
#define T_BLO 49152
#define GEMM_SMEM (2*STAGE_BYTES + 32)

template<int WRITE_F32, int WRITE_HILO, int RELU>
__global__ void __launch_bounds__(256, 1) gemm_mma_kernel(
    const __grid_constant__ CUtensorMap mAhi,
    const __grid_constant__ CUtensorMap mAlo,
    const __grid_constant__ CUtensorMap mBhi,
    const __grid_constant__ CUtensorMap mBlo,
    const float* __restrict__ bias,
    float* __restrict__ C, __nv_bfloat16* __restrict__ Chi, __nv_bfloat16* __restrict__ Clo,
    int M, int N, int K)
{
    extern __shared__ char smem[];
    const uint32_t sbase = smem_to_u32(smem);
    const uint32_t mb0 = sbase + 2 * STAGE_BYTES;
    const uint32_t mb1 = mb0 + 8;
    const int tid = threadIdx.x;
    const int wid = tid >> 5;
    const int lane = tid & 31;
    const int g = lane >> 2;
    const int tq = lane & 3;
    const int wm = wid & 3;
    const int wn = wid >> 2;
    const int bm = blockIdx.y * 128;
    const int bn = blockIdx.x * 128;
    const int nst = K >> 6;

    if (tid == 0) {
        MBARRIER_INIT(mb0, 1);
        MBARRIER_INIT(mb1, 1);
    }
    FENCE_ASYNC_SHARED();
    __syncthreads();

    if (tid == 0) {
#pragma unroll
        for (int s = 0; s < 2; s++) {
            uint32_t mb = (s == 0) ? mb0 : mb1;
            uint32_t dst = sbase + s * STAGE_BYTES;
            MBARRIER_EXPECT_TX(mb, STAGE_BYTES);
            tma_load_2d(dst + T_AHI, &mAhi, s * 64, bm, mb);
            tma_load_2d(dst + T_ALO, &mAlo, s * 64, bm, mb);
            tma_load_2d(dst + T_BHI, &mBhi, s * 64, bn, mb);
            tma_load_2d(dst + T_BLO, &mBlo, s * 64, bn, mb);
        }
    }

    float acc[2][8][4];
#pragma unroll
    for (int t = 0; t < 2; t++)
#pragma unroll
        for (int j = 0; j < 8; j++)
#pragma unroll
            for (int q = 0; q < 4; q++) acc[t][j][q] = 0.f;

    const int arow0 = wm * 32 + g;
    const int brow0 = wn * 64 + g;

    for (int s = 0; s < nst; s++) {
        MBARRIER_WAIT_PARITY((s & 1) ? mb1 : mb0, (s >> 1) & 1);
        const char* buf = smem + (s & 1) * STAGE_BYTES;

#pragma unroll
        for (int ks = 0; ks < 4; ks++) {
            const int c0 = ks * 32 + tq * 4;
            const int c1 = c0 + 16;
            uint32_t ah[2][4], al[2][4];
#pragma unroll
            for (int t = 0; t < 2; t++) {
                int r0 = arow0 + t * 16, r1 = r0 + 8;
                ah[t][0] = *(const uint32_t*)(buf + T_AHI + swoff(r0, c0));
                ah[t][1] = *(const uint32_t*)(buf + T_AHI + swoff(r1, c0));
                ah[t][2] = *(const uint32_t*)(buf + T_AHI + swoff(r0, c1));
                ah[t][3] = *(const uint32_t*)(buf + T_AHI + swoff(r1, c1));
                al[t][0] = *(const uint32_t*)(buf + T_ALO + swoff(r0, c0));
                al[t][1] = *(const uint32_t*)(buf + T_ALO + swoff(r1, c0));
                al[t][2] = *(const uint32_t*)(buf + T_ALO + swoff(r0, c1));
                al[t][3] = *(const uint32_t*)(buf + T_ALO + swoff(r1, c1));
            }
            uint32_t bh[8][2], bl[8][2];
#pragma unroll
            for (int j = 0; j < 8; j++) {
                int rn = brow0 + j * 8;
                bh[j][0] = *(const uint32_t*)(buf + T_BHI + swoff(rn, c0));
                bh[j][1] = *(const uint32_t*)(buf + T_BHI + swoff(rn, c1));
                bl[j][0] = *(const uint32_t*)(buf + T_BLO + swoff(rn, c0));
                bl[j][1] = *(const uint32_t*)(buf + T_BLO + swoff(rn, c1));
            }
#pragma unroll
            for (int t = 0; t < 2; t++)
#pragma unroll
                for (int j = 0; j < 8; j++) {
                    mma_bf16(acc[t][j], ah[t], bh[j]);
                    mma_bf16(acc[t][j], ah[t], bl[j]);
                    mma_bf16(acc[t][j], al[t], bh[j]);
                }
        }

        __syncthreads();
        if (tid == 0 && s + 2 < nst) {
            uint32_t mb = (s & 1) ? mb1 : mb0;
            uint32_t dst = sbase + (s & 1) * STAGE_BYTES;
            MBARRIER_EXPECT_TX(mb, STAGE_BYTES);
            tma_load_2d(dst + T_AHI, &mAhi, (s + 2) * 64, bm, mb);
            tma_load_2d(dst + T_ALO, &mAlo, (s + 2) * 64, bm, mb);
            tma_load_2d(dst + T_BHI, &mBhi, (s + 2) * 64, bn, mb);
            tma_load_2d(dst + T_BLO, &mBlo, (s + 2) * 64, bn, mb);
        }
    }

#pragma unroll
    for (int t = 0; t < 2; t++) {
        int row = bm + wm * 32 + t * 16 + g;
#pragma unroll
        for (int j = 0; j < 8; j++) {
            int col = bn + wn * 64 + j * 8 + tq * 2;
            float2 bj = *(const float2*)&bias[col];
            float v0 = acc[t][j][0] + bj.x;
            float v1 = acc[t][j][1] + bj.y;
            float v2 = acc[t][j][2] + bj.x;
            float v3 = acc[t][j][3] + bj.y;
            if (RELU) {
                v0 = fmaxf(v0, 0.f); v1 = fmaxf(v1, 0.f);
                v2 = fmaxf(v2, 0.f); v3 = fmaxf(v3, 0.f);
            }
            if (WRITE_F32) {
                *(float2*)&C[(size_t)row * N + col]       = make_float2(v0, v1);
                *(float2*)&C[(size_t)(row + 8) * N + col] = make_float2(v2, v3);
            }
            if (WRITE_HILO) {
                uint32_t h01, l01, h23, l23;
                split_pack2(v0, v1, h01, l01);
                split_pack2(v2, v3, h23, l23);
                *(uint32_t*)&Chi[(size_t)row * N + col]       = h01;
                *(uint32_t*)&Chi[(size_t)(row + 8) * N + col] = h23;
                *(uint32_t*)&Clo[(size_t)row * N + col]       = l01;
                *(uint32_t*)&Clo[(size_t)(row + 8) * N + col] = l23;
            }
        }
    }
}

// ---------------- V transpose: V[s*4+b][d] -> VT[(b*DM+d)][s] -----------------
// tile: 32 s x 64 d per (b); grid (SLEN/32, DMODEL/64, BATCH), 256 threads
__global__ void __launch_bounds__(256) transpose_v_kernel(
    const __nv_bfloat16* __restrict__ Vhi, const __nv_bfloat16* __restrict__ Vlo,
    __nv_bfloat16* __restrict__ VThi, __nv_bfloat16* __restrict__ VTlo)
{
    __shared__ __nv_bfloat16 sh[32][64 + 4];
    __shared__ __nv_bfloat16 sl[32][64 + 4];
    const int tid = threadIdx.x;
    const int s0 = blockIdx.x * 32;
    const int d0 = blockIdx.y * 64;
    const int b  = blockIdx.z;

#pragma unroll
    for (int p = 0; p < 2; p++) {
        int idx = tid + p * 256;          // 0..511
        int srow = idx >> 4;              // 0..31
        int dq = idx & 15;                // 16 quads of 4 d
        size_t ga = ((size_t)(s0 + srow) * BATCH + b) * DMODEL + d0 + dq * 4;
        uint2 vh = *(const uint2*)(Vhi + ga);
        uint2 vl = *(const uint2*)(Vlo + ga);
        *(uint2*)&sh[srow][dq * 4] = vh;
        *(uint2*)&sl[srow][dq * 4] = vl;
    }
    __syncthreads();
#pragma unroll
    for (int p = 0; p < 2; p++) {
        int idx = tid + p * 256;          // 0..511
        int drow = idx >> 3;              // 0..63
        int sq = idx & 7;                 // 8 quads of 4 s
        __nv_bfloat16 oh[4], ol[4];
#pragma unroll
        for (int k = 0; k < 4; k++) {
            oh[k] = sh[sq * 4 + k][drow];
            ol[k] = sl[sq * 4 + k][drow];
        }
        size_t ga = ((size_t)(b * DMODEL + d0 + drow)) * SLEN + s0 + sq * 4;
        *(uint2*)(VThi + ga) = *(uint2*)oh;
        *(uint2*)(VTlo + ga) = *(uint2*)ol;
    }
}

// ---------------- Flash attention on mma.sync (split-bf16) --------------------
// CTA: 128 queries x one (b,h). 8 warps x 16 query rows. 64-key stages, 2 bufs.
// smem: Qhi 16K | Qlo 16K | stage{Khi 8K, Klo 8K, Vhi 8K, Vlo 8K} x2 | ctrl
#define ATT_QHI 0
#define ATT_QLO 16384
#define ATT_ST0 32768
#define ATT_STSZ 32768
#define ATT_CTRL (ATT_ST0 + 2*ATT_STSZ)
#define ATT_SMEM (ATT_CTRL + 64)
#define NKT (SLEN/64)   // 32 key tiles

__global__ void __launch_bounds__(256, 1) attn_mma_kernel(
    const __grid_constant__ CUtensorMap mQhi, const __grid_constant__ CUtensorMap mQlo,
    const __grid_constant__ CUtensorMap mKhi, const __grid_constant__ CUtensorMap mKlo,
    const __grid_constant__ CUtensorMap mVhi, const __grid_constant__ CUtensorMap mVlo,
    __nv_bfloat16* __restrict__ Ohi, __nv_bfloat16* __restrict__ Olo)
{
    extern __shared__ char smem[];
    const uint32_t sbase = smem_to_u32(smem);
    const uint32_t mb0 = sbase + ATT_CTRL;
    const uint32_t mb1 = mb0 + 8;
    const int tid = threadIdx.x;
    const int w = tid >> 5;
    const int lane = tid & 31;
    const int g = lane >> 2;
    const int t = lane & 3;
    const int q0 = blockIdx.x * 128;
    const int b = blockIdx.y >> 4;
    const int h = blockIdx.y & 15;
    const int xqk = b * DMODEL + h * 64;   // column coord into [s][(b,d)] view

    if (tid == 0) {
        MBARRIER_INIT(mb0, 1);
        MBARRIER_INIT(mb1, 1);
    }
    FENCE_ASYNC_SHARED();
    __syncthreads();

    if (tid == 0) {
        // stage 0 + Q
        MBARRIER_EXPECT_TX(mb0, ATT_STSZ + 32768);
        tma_load_2d(sbase + ATT_QHI, &mQhi, xqk, q0, mb0);
        tma_load_2d(sbase + ATT_QLO, &mQlo, xqk, q0, mb0);
        tma_load_2d(sbase + ATT_ST0 + 0,     &mKhi, xqk, 0, mb0);
        tma_load_2d(sbase + ATT_ST0 + 8192,  &mKlo, xqk, 0, mb0);
        tma_load_2d(sbase + ATT_ST0 + 16384, &mVhi, 0, xqk, mb0);
        tma_load_2d(sbase + ATT_ST0 + 24576, &mVlo, 0, xqk, mb0);
        // stage 1
        MBARRIER_EXPECT_TX(mb1, ATT_STSZ);
        tma_load_2d(sbase + ATT_ST0 + ATT_STSZ + 0,     &mKhi, xqk, 64, mb1);
        tma_load_2d(sbase + ATT_ST0 + ATT_STSZ + 8192,  &mKlo, xqk, 64, mb1);
        tma_load_2d(sbase + ATT_ST0 + ATT_STSZ + 16384, &mVhi, 64, xqk, mb1);
        tma_load_2d(sbase + ATT_ST0 + ATT_STSZ + 24576, &mVlo, 64, xqk, mb1);
    }

    float m_i[2] = {-1e30f, -1e30f};
    float l_i[2] = {0.f, 0.f};
    float acc[8][4];
#pragma unroll
    for (int j = 0; j < 8; j++)
#pragma unroll
        for (int q = 0; q < 4; q++) acc[j][q] = 0.f;

    const int qr0 = w * 16 + g;     // local query row (and +8)

    for (int s = 0; s < NKT; s++) {
        MBARRIER_WAIT_PARITY((s & 1) ? mb1 : mb0, (s >> 1) & 1);
        const char* Kb = smem + ATT_ST0 + (s & 1) * ATT_STSZ;
        const char* Vb = Kb + 16384;

        // ---- scores = Q K^T (3-term split) ----
        float sc[8][4];
#pragma unroll
        for (int j = 0; j < 8; j++)
#pragma unroll
            for (int q = 0; q < 4; q++) sc[j][q] = 0.f;

#pragma unroll
        for (int ks = 0; ks < 4; ks++) {
            const int c0 = ks * 32 + t * 4;
            const int c1 = c0 + 16;
            uint32_t qh[4], ql[4];
            qh[0] = *(const uint32_t*)(smem + ATT_QHI + swoff(qr0, c0));
            qh[1] = *(const uint32_t*)(smem + ATT_QHI + swoff(qr0 + 8, c0));
            qh[2] = *(const uint32_t*)(smem + ATT_QHI + swoff(qr0, c1));
            qh[3] = *(const uint32_t*)(smem + ATT_QHI + swoff(qr0 + 8, c1));
            ql[0] = *(const uint32_t*)(smem + ATT_QLO + swoff(qr0, c0));
            ql[1] = *(const uint32_t*)(smem + ATT_QLO + swoff(qr0 + 8, c0));
            ql[2] = *(const uint32_t*)(smem + ATT_QLO + swoff(qr0, c1));
            ql[3] = *(const uint32_t*)(smem + ATT_QLO + swoff(qr0 + 8, c1));
#pragma unroll
            for (int j = 0; j < 8; j++) {
                const int rn = j * 8 + g;
                uint32_t kh[2], kl[2];
                kh[0] = *(const uint32_t*)(Kb + swoff(rn, c0));
                kh[1] = *(const uint32_t*)(Kb + swoff(rn, c1));
                kl[0] = *(const uint32_t*)(Kb + 8192 + swoff(rn, c0));
                kl[1] = *(const uint32_t*)(Kb + 8192 + swoff(rn, c1));
                mma_bf16(sc[j], qh, kh);
                mma_bf16(sc[j], qh, kl);
                mma_bf16(sc[j], ql, kh);
            }
        }

        // ---- online softmax (rows qr0 and qr0+8, each in a lane quad) ----
        float mx0 = -1e30f, mx1 = -1e30f;
#pragma unroll
        for (int j = 0; j < 8; j++) {
            sc[j][0] *= 0.125f; sc[j][1] *= 0.125f;
            sc[j][2] *= 0.125f; sc[j][3] *= 0.125f;
            mx0 = fmaxf(mx0, fmaxf(sc[j][0], sc[j][1]));
            mx1 = fmaxf(mx1, fmaxf(sc[j][2], sc[j][3]));
        }
        mx0 = fmaxf(mx0, __shfl_xor_sync(0xffffffffu, mx0, 1));
        mx0 = fmaxf(mx0, __shfl_xor_sync(0xffffffffu, mx0, 2));
        mx1 = fmaxf(mx1, __shfl_xor_sync(0xffffffffu, mx1, 1));
        mx1 = fmaxf(mx1, __shfl_xor_sync(0xffffffffu, mx1, 2));
        float mn0 = fmaxf(m_i[0], mx0);
        float mn1 = fmaxf(m_i[1], mx1);
        float a0 = __expf(m_i[0] - mn0);
        float a1 = __expf(m_i[1] - mn1);
        m_i[0] = mn0; m_i[1] = mn1;
        float s0 = 0.f, s1 = 0.f;
#pragma unroll
        for (int j = 0; j < 8; j++) {
            sc[j][0] = __expf(sc[j][0] - mn0);
            sc[j][1] = __expf(sc[j][1] - mn0);
            sc[j][2] = __expf(sc[j][2] - mn1);
            sc[j][3] = __expf(sc[j][3] - mn1);
            s0 += sc[j][0] + sc[j][1];
            s1 += sc[j][2] + sc[j][3];
        }
        s0 += __shfl_xor_sync(0xffffffffu, s0, 1);
        s0 += __shfl_xor_sync(0xffffffffu, s0, 2);
        s1 += __shfl_xor_sync(0xffffffffu, s1, 1);
        s1 += __shfl_xor_sync(0xffffffffu, s1, 2);
        l_i[0] = l_i[0] * a0 + s0;
        l_i[1] = l_i[1] * a1 + s1;
#pragma unroll
        for (int j = 0; j < 8; j++) {
            acc[j][0] *= a0; acc[j][1] *= a0;
            acc[j][2] *= a1; acc[j][3] *= a1;
        }

        // ---- ctx += P V (3-term split; P a-frags from c-frag registers) ----
#pragma unroll
        for (int ks = 0; ks < 4; ks++) {
            uint32_t pah[4], pal[4];
            split_pack2(sc[2*ks][0],   sc[2*ks][1],   pah[0], pal[0]);
            split_pack2(sc[2*ks][2],   sc[2*ks][3],   pah[1], pal[1]);
            split_pack2(sc[2*ks+1][0], sc[2*ks+1][1], pah[2], pal[2]);
            split_pack2(sc[2*ks+1][2], sc[2*ks+1][3], pah[3], pal[3]);
            const int c0 = ks * 32 + t * 4;
            const int c1 = c0 + 16;
#pragma unroll
            for (int j = 0; j < 8; j++) {
                const int rn = j * 8 + g;
                uint32_t vh[2], vl[2];
                vh[0] = *(const uint32_t*)(Vb + swoff(rn, c0));
                vh[1] = *(const uint32_t*)(Vb + swoff(rn, c1));
                vl[0] = *(const uint32_t*)(Vb + 8192 + swoff(rn, c0));
                vl[1] = *(const uint32_t*)(Vb + 8192 + swoff(rn, c1));
                mma_bf16(acc[j], pah, vh);
                mma_bf16(acc[j], pah, vl);
                mma_bf16(acc[j], pal, vh);
            }
        }

        __syncthreads();
        if (tid == 0 && s + 2 < NKT) {
            uint32_t mb = (s & 1) ? mb1 : mb0;
            uint32_t dst = sbase + ATT_ST0 + (s & 1) * ATT_STSZ;
            MBARRIER_EXPECT_TX(mb, ATT_STSZ);
            tma_load_2d(dst + 0,     &mKhi, xqk, (s + 2) * 64, mb);
            tma_load_2d(dst + 8192,  &mKlo, xqk, (s + 2) * 64, mb);
            tma_load_2d(dst + 16384, &mVhi, (s + 2) * 64, xqk, mb);
            tma_load_2d(dst + 24576, &mVlo, (s + 2) * 64, xqk, mb);
        }
    }

    // ---- epilogue: ctx / l -> bf16 hi/lo into [NTOK][DM] ----
    const float inv0 = 1.0f / l_i[0];
    const float inv1 = 1.0f / l_i[1];
    const int row0 = q0 + qr0;
    const int row1 = row0 + 8;
    const size_t tok0 = (size_t)row0 * BATCH + b;
    const size_t tok1 = (size_t)row1 * BATCH + b;
#pragma unroll
    for (int j = 0; j < 8; j++) {
        const int col = h * 64 + j * 8 + t * 2;
        uint32_t h01, l01, h23, l23;
        split_pack2(acc[j][0] * inv0, acc[j][1] * inv0, h01, l01);
        split_pack2(acc[j][2] * inv1, acc[j][3] * inv1, h23, l23);
        *(uint32_t*)&Ohi[tok0 * DMODEL + col] = h01;
        *(uint32_t*)&Olo[tok0 * DMODEL + col] = l01;
        *(uint32_t*)&Ohi[tok1 * DMODEL + col] = h23;
        *(uint32_t*)&Olo[tok1 * DMODEL + col] = l23;
    }
}

// ---------------- fused residual add + LayerNorm -----------------------------
template<int HILO>
__global__ void __launch_bounds__(256) add_ln_kernel(
    const float* __restrict__ A, const float* __restrict__ R,
    const float* __restrict__ gam, const float* __restrict__ bet,
    float* __restrict__ out, __nv_bfloat16* __restrict__ Ohi,
    __nv_bfloat16* __restrict__ Olo)
{
    __shared__ float red_s[8];
    __shared__ float red_ss[8];
    __shared__ float s_mu, s_rstd;
    const int row = blockIdx.x;
    const int t = threadIdx.x;
    const float4* a4 = (const float4*)(A + (size_t)row * DMODEL);
    const float4* r4 = (const float4*)(R + (size_t)row * DMODEL);
    float4 v = a4[t];
    float4 w = r4[t];
    v.x += w.x; v.y += w.y; v.z += w.z; v.w += w.w;
    float s = v.x + v.y + v.z + v.w;
    float ss = v.x * v.x + v.y * v.y + v.z * v.z + v.w * v.w;
#pragma unroll
    for (int off = 16; off >= 1; off >>= 1) {
        s  += __shfl_xor_sync(0xffffffffu, s, off);
        ss += __shfl_xor_sync(0xffffffffu, ss, off);
    }
    if ((t & 31) == 0) { red_s[t >> 5] = s; red_ss[t >> 5] = ss; }
    __syncthreads();
    if (t == 0) {
        float ts = 0.f, tss = 0.f;
#pragma unroll
        for (int i = 0; i < 8; i++) { ts += red_s[i]; tss += red_ss[i]; }
        float mu = ts * (1.0f / DMODEL);
        float var = tss * (1.0f / DMODEL) - mu * mu;
        s_mu = mu;
        s_rstd = rsqrtf(var + LN_EPS);
    }
    __syncthreads();
    float mu = s_mu, rs = s_rstd;
    float4 g = ((const float4*)gam)[t], bb = ((const float4*)bet)[t];
    float4 o;
    o.x = (v.x - mu) * rs * g.x + bb.x;
    o.y = (v.y - mu) * rs * g.y + bb.y;
    o.z = (v.z - mu) * rs * g.z + bb.z;
    o.w = (v.w - mu) * rs * g.w + bb.w;
    ((float4*)(out + (size_t)row * DMODEL))[t] = o;
    if (HILO) {
        uint2 uh, ul;
        split_pack2(o.x, o.y, uh.x, ul.x);
        split_pack2(o.z, o.w, uh.y, ul.y);
        ((uint2*)(Ohi + (size_t)row * DMODEL))[t] = uh;
        ((uint2*)(Olo + (size_t)row * DMODEL))[t] = ul;
    }
}

// ---------------- host: tensormap + launch ------------------------------------
typedef CUresult (*EncodeFn)(
    CUtensorMap*, CUtensorMapDataType, cuuint32_t, void*,
    const cuuint64_t*, const cuuint64_t*, const cuuint32_t*, const cuuint32_t*,
    CUtensorMapInterleave, CUtensorMapSwizzle, CUtensorMapL2promotion,
    CUtensorMapFloatOOBfill);

static void make_desc(EncodeFn enc, CUtensorMap* out, void* ptr,
                      uint64_t rows, uint64_t K, uint32_t box1)
{
    cuuint64_t dims[2]    = {K, rows};
    cuuint64_t strides[1] = {K * 2};
    cuuint32_t box[2]     = {64, box1};
    cuuint32_t estr[2]    = {1, 1};
    enc(out, CU_TENSOR_MAP_DATA_TYPE_BFLOAT16, 2, ptr, dims, strides, box, estr,
        CU_TENSOR_MAP_INTERLEAVE_NONE, CU_TENSOR_MAP_SWIZZLE_128B,
        CU_TENSOR_MAP_L2_PROMOTION_L2_128B, CU_TENSOR_MAP_FLOAT_OOB_FILL_NONE);
}

extern "C" void kernel_launch(void* const* d_in, const int* in_sizes, int n_in,
                              void* d_out, int out_size)
{
    const float* X    = (const float*)d_in[0];
    const float* WQw  = (const float*)d_in[1];
    const float* WQb  = (const float*)d_in[2];
    const float* WKw  = (const float*)d_in[3];
    const float* WKb  = (const float*)d_in[4];
    const float* WVw  = (const float*)d_in[5];
    const float* WVb  = (const float*)d_in[6];
    const float* WOw  = (const float*)d_in[7];
    const float* WOb  = (const float*)d_in[8];
    const float* ln1g = (const float*)d_in[9];
    const float* ln1b = (const float*)d_in[10];
    const float* W1   = (const float*)d_in[11];
    const float* b1   = (const float*)d_in[12];
    const float* W2   = (const float*)d_in[13];
    const float* b2   = (const float*)d_in[14];
    const float* ln2g = (const float*)d_in[15];
    const float* ln2b = (const float*)d_in[16];
    float* out = (float*)d_out;

    float *Y, *X1, *M;
    cudaGetSymbolAddress((void**)&Y,  g_Y);
    cudaGetSymbolAddress((void**)&X1, g_X1);
    cudaGetSymbolAddress((void**)&M,  g_M);

    __nv_bfloat16 *Xhi,*Xlo,*X1hi,*X1lo,*CTXhi,*CTXlo,*HIDhi,*HIDlo;
    __nv_bfloat16 *Qhi,*Qlo,*Khi,*Klo,*Vhi,*Vlo,*VThi,*VTlo;
    __nv_bfloat16 *WQhi,*WQlo,*WKhi,*WKlo,*WVhi,*WVlo,*WOhi,*WOlo,*W1hi,*W1lo,*W2hi,*W2lo;
    cudaGetSymbolAddress((void**)&Xhi,  g_Xhi);  cudaGetSymbolAddress((void**)&Xlo,  g_Xlo);
    cudaGetSymbolAddress((void**)&X1hi, g_X1hi); cudaGetSymbolAddress((void**)&X1lo, g_X1lo);
    cudaGetSymbolAddress((void**)&CTXhi,g_CTXhi);cudaGetSymbolAddress((void**)&CTXlo,g_CTXlo);
    cudaGetSymbolAddress((void**)&Qhi,  g_Qhi);  cudaGetSymbolAddress((void**)&Qlo,  g_Qlo);
    cudaGetSymbolAddress((void**)&Khi,  g_Khi);  cudaGetSymbolAddress((void**)&Klo,  g_Klo);
    cudaGetSymbolAddress((void**)&Vhi,  g_Vhi);  cudaGetSymbolAddress((void**)&Vlo,  g_Vlo);
    cudaGetSymbolAddress((void**)&VThi, g_VThi); cudaGetSymbolAddress((void**)&VTlo, g_VTlo);
    cudaGetSymbolAddress((void**)&HIDhi,g_HIDhi);cudaGetSymbolAddress((void**)&HIDlo,g_HIDlo);
    cudaGetSymbolAddress((void**)&WQhi, g_WQhi); cudaGetSymbolAddress((void**)&WQlo, g_WQlo);
    cudaGetSymbolAddress((void**)&WKhi, g_WKhi); cudaGetSymbolAddress((void**)&WKlo, g_WKlo);
    cudaGetSymbolAddress((void**)&WVhi, g_WVhi); cudaGetSymbolAddress((void**)&WVlo, g_WVlo);
    cudaGetSymbolAddress((void**)&WOhi, g_WOhi); cudaGetSymbolAddress((void**)&WOlo, g_WOlo);
    cudaGetSymbolAddress((void**)&W1hi, g_W1hi); cudaGetSymbolAddress((void**)&W1lo, g_W1lo);
    cudaGetSymbolAddress((void**)&W2hi, g_W2hi); cudaGetSymbolAddress((void**)&W2lo, g_W2lo);

    EncodeFn enc = nullptr;
    {
        void* fp = nullptr;
        cudaDriverEntryPointQueryResult qr;
        cudaGetDriverEntryPoint("cuTensorMapEncodeTiled", &fp, cudaEnableDefault, &qr);
        enc = (EncodeFn)fp;
    }

    // GEMM descriptors (box 64x128)
    CUtensorMap dXhi, dXlo, dWQhi, dWQlo, dWKhi, dWKlo, dWVhi, dWVlo;
    CUtensorMap dCTXhi, dCTXlo, dWOhi, dWOlo;
    CUtensorMap dX1hi, dX1lo, dW1hi, dW1lo, dHIDhi, dHIDlo, dW2hi, dW2lo;
    make_desc(enc, &dXhi,  Xhi,  NTOK, DMODEL, 128);  make_desc(enc, &dXlo,  Xlo,  NTOK, DMODEL, 128);
    make_desc(enc, &dWQhi, WQhi, DMODEL, DMODEL, 128);make_desc(enc, &dWQlo, WQlo, DMODEL, DMODEL, 128);
    make_desc(enc, &dWKhi, WKhi, DMODEL, DMODEL, 128);make_desc(enc, &dWKlo, WKlo, DMODEL, DMODEL, 128);
    make_desc(enc, &dWVhi, WVhi, DMODEL, DMODEL, 128);make_desc(enc, &dWVlo, WVlo, DMODEL, DMODEL, 128);
    make_desc(enc, &dCTXhi,CTXhi,NTOK, DMODEL, 128);  make_desc(enc, &dCTXlo,CTXlo,NTOK, DMODEL, 128);
    make_desc(enc, &dWOhi, WOhi, DMODEL, DMODEL, 128);make_desc(enc, &dWOlo, WOlo, DMODEL, DMODEL, 128);
    make_desc(enc, &dX1hi, X1hi, NTOK, DMODEL, 128);  make_desc(enc, &dX1lo, X1lo, NTOK, DMODEL, 128);
    make_desc(enc, &dW1hi, W1hi, DFFN, DMODEL, 128);  make_desc(enc, &dW1lo, W1lo, DFFN, DMODEL, 128);
    make_desc(enc, &dHIDhi,HIDhi,NTOK, DFFN, 128);    make_desc(enc, &dHIDlo,HIDlo,NTOK, DFFN, 128);
    make_desc(enc, &dW2hi, W2hi, DMODEL, DFFN, 128);  make_desc(enc, &dW2lo, W2lo, DMODEL, DFFN, 128);

    // attention descriptors: Q/K as [s] x [b*DM+d] view; VT as [b*DM+d] x [s]
    CUtensorMap dQhi, dQlo, dKhi, dKlo, dVThi, dVTlo;
    make_desc(enc, &dQhi, Qhi, SLEN, BATCH*DMODEL, 128);
    make_desc(enc, &dQlo, Qlo, SLEN, BATCH*DMODEL, 128);
    make_desc(enc, &dKhi, Khi, SLEN, BATCH*DMODEL, 64);
    make_desc(enc, &dKlo, Klo, SLEN, BATCH*DMODEL, 64);
    make_desc(enc, &dVThi, VThi, BATCH*DMODEL, SLEN, 64);
    make_desc(enc, &dVTlo, VTlo, BATCH*DMODEL, SLEN, 64);

    cudaFuncSetAttribute(gemm_mma_kernel<1,0,0>, cudaFuncAttributeMaxDynamicSharedMemorySize, GEMM_SMEM);
    cudaFuncSetAttribute(gemm_mma_kernel<0,1,1>, cudaFuncAttributeMaxDynamicSharedMemorySize, GEMM_SMEM);
    cudaFuncSetAttribute(gemm_mma_kernel<0,1,0>, cudaFuncAttributeMaxDynamicSharedMemorySize, GEMM_SMEM);
    cudaFuncSetAttribute(attn_mma_kernel, cudaFuncAttributeMaxDynamicSharedMemorySize, ATT_SMEM);

    // ---- fp32 -> bf16 hi/lo splits ----
    cvt_kernel<<<(NTOK*DMODEL/4 + 255)/256, 256>>>(X,   Xhi,  Xlo,  NTOK*DMODEL/4);
    cvt_kernel<<<(DMODEL*DMODEL/4 + 255)/256, 256>>>(WQw, WQhi, WQlo, DMODEL*DMODEL/4);
    cvt_kernel<<<(DMODEL*DMODEL/4 + 255)/256, 256>>>(WKw, WKhi, WKlo, DMODEL*DMODEL/4);
    cvt_kernel<<<(DMODEL*DMODEL/4 + 255)/256, 256>>>(WVw, WVhi, WVlo, DMODEL*DMODEL/4);
    cvt_kernel<<<(DMODEL*DMODEL/4 + 255)/256, 256>>>(WOw, WOhi, WOlo, DMODEL*DMODEL/4);
    cvt_kernel<<<(DFFN*DMODEL/4 + 255)/256, 256>>>(W1,  W1hi, W1lo, DFFN*DMODEL/4);
    cvt_kernel<<<(DMODEL*DFFN/4 + 255)/256, 256>>>(W2,  W2hi, W2lo, DMODEL*DFFN/4);

    dim3 gProj(DMODEL / 128, NTOK / 128);   // 8 x 64
    dim3 gFF1(DFFN / 128, NTOK / 128);      // 32 x 64

    // ---- QKV projections (emit bf16 hi/lo) ----
    gemm_mma_kernel<0,1,0><<<gProj, 256, GEMM_SMEM>>>(dXhi, dXlo, dWQhi, dWQlo, WQb, nullptr, Qhi, Qlo, NTOK, DMODEL, DMODEL);
    gemm_mma_kernel<0,1,0><<<gProj, 256, GEMM_SMEM>>>(dXhi, dXlo, dWKhi, dWKlo, WKb, nullptr, Khi, Klo, NTOK, DMODEL, DMODEL);
    gemm_mma_kernel<0,1,0><<<gProj, 256, GEMM_SMEM>>>(dXhi, dXlo, dWVhi, dWVlo, WVb, nullptr, Vhi, Vlo, NTOK, DMODEL, DMODEL);

    // ---- V transpose for PV operand ----
    transpose_v_kernel<<<dim3(SLEN/32, DMODEL/64, BATCH), 256>>>(Vhi, Vlo, VThi, VTlo);

    // ---- attention (mma.sync split-bf16) ----
    attn_mma_kernel<<<dim3(SLEN/128, BATCH*NHEAD), 256, ATT_SMEM>>>(
        dQhi, dQlo, dKhi, dKlo, dVThi, dVTlo, CTXhi, CTXlo);

    // ---- output projection + residual LN1 ----
    gemm_mma_kernel<1,0,0><<<gProj, 256, GEMM_SMEM>>>(dCTXhi, dCTXlo, dWOhi, dWOlo, WOb, Y, nullptr, nullptr, NTOK, DMODEL, DMODEL);
    add_ln_kernel<1><<<NTOK, 256>>>(Y, X, ln1g, ln1b, X1, X1hi, X1lo);

    // ---- MLP ----
    gemm_mma_kernel<0,1,1><<<gFF1, 256, GEMM_SMEM>>>(dX1hi, dX1lo, dW1hi, dW1lo, b1, nullptr, HIDhi, HIDlo, NTOK, DFFN, DMODEL);
    gemm_mma_kernel<1,0,0><<<gProj, 256, GEMM_SMEM>>>(dHIDhi, dHIDlo, dW2hi, dW2lo, b2, M, nullptr, nullptr, NTOK, DMODEL, DFFN);
    add_ln_kernel<0><<<NTOK, 256>>>(M, X1, ln2g, ln2b, out, nullptr, nullptr);
}

// round 5
// speedup vs baseline: 5.3215x; 1.0834x over previous
#include <cuda_runtime.h>
#include <cuda.h>
#include <cuda_bf16.h>
#include <cstdint>

#define SLEN 2048
#define BATCH 4
#define DMODEL 1024
#define NHEAD 16
#define DKH 64
#define DFFN 4096
#define NTOK (SLEN*BATCH)   // 8192
#define LN_EPS 1e-5f
#define QSCALE 0.18033688011112042f   // 0.125 * log2(e)

// ---------------- scratch (device globals) ----------------------------------
__device__ __align__(1024) float g_Y[NTOK*DMODEL];
__device__ __align__(1024) float g_X1[NTOK*DMODEL];
__device__ __align__(1024) float g_M[NTOK*DMODEL];

__device__ __align__(1024) __nv_bfloat16 g_Xhi[NTOK*DMODEL],  g_Xlo[NTOK*DMODEL];
__device__ __align__(1024) __nv_bfloat16 g_X1hi[NTOK*DMODEL], g_X1lo[NTOK*DMODEL];
__device__ __align__(1024) __nv_bfloat16 g_CTXhi[NTOK*DMODEL],g_CTXlo[NTOK*DMODEL];
__device__ __align__(1024) __nv_bfloat16 g_Qhi[NTOK*DMODEL],  g_Qlo[NTOK*DMODEL];
__device__ __align__(1024) __nv_bfloat16 g_Khi[NTOK*DMODEL],  g_Klo[NTOK*DMODEL];
__device__ __align__(1024) __nv_bfloat16 g_Vhi[NTOK*DMODEL],  g_Vlo[NTOK*DMODEL];
__device__ __align__(1024) __nv_bfloat16 g_VThi[NTOK*DMODEL], g_VTlo[NTOK*DMODEL];
__device__ __align__(1024) __nv_bfloat16 g_HIDhi[NTOK*DFFN],  g_HIDlo[NTOK*DFFN];
__device__ __align__(1024) __nv_bfloat16 g_WQKVhi[3*DMODEL*DMODEL], g_WQKVlo[3*DMODEL*DMODEL];
__device__ __align__(1024) __nv_bfloat16 g_WOhi[DMODEL*DMODEL], g_WOlo[DMODEL*DMODEL];
__device__ __align__(1024) __nv_bfloat16 g_W1hi[DFFN*DMODEL],   g_W1lo[DFFN*DMODEL];
__device__ __align__(1024) __nv_bfloat16 g_W2hi[DMODEL*DFFN],   g_W2lo[DMODEL*DFFN];

// ---------------- PTX helpers (base-ISA only) --------------------------------
__device__ __forceinline__ uint32_t smem_to_u32(const void* p) {
    uint32_t a;
    asm("{ .reg .u64 t; cvta.to.shared.u64 t, %1; cvt.u32.u64 %0, t; }" : "=r"(a) : "l"(p));
    return a;
}
#define MBARRIER_INIT(mbar, cnt) \
    asm volatile("mbarrier.init.shared.b64 [%0], %1;" :: "r"((uint32_t)(mbar)), "r"((uint32_t)(cnt)) : "memory")
#define MBARRIER_EXPECT_TX(mbar, bytes) \
    asm volatile("mbarrier.arrive.expect_tx.shared.b64 _, [%0], %1;" :: "r"((uint32_t)(mbar)), "r"((uint32_t)(bytes)) : "memory")
#define FENCE_ASYNC_SHARED() asm volatile("fence.proxy.async.shared::cta;" ::: "memory")

#define MBARRIER_WAIT_PARITY(mbar_smem_addr, phase_parity) do { \
    uint32_t _mbar = (uint32_t)(mbar_smem_addr); \
    uint32_t _parity = (uint32_t)(phase_parity); \
    uint32_t _done; \
    asm volatile("{ .reg .pred p; mbarrier.try_wait.parity.acquire.cta.shared::cta.b64 p, [%1], %2; selp.b32 %0, 1, 0, p; }" \
        : "=r"(_done) : "r"(_mbar), "r"(_parity) : "memory"); \
    if (!_done) { \
        asm volatile("{ .reg .pred P1; WAIT_LOOP_%=: mbarrier.try_wait.parity.acquire.cta.shared::cta.b64 P1, [%0], %1, 0x989680; @P1 bra.uni WAIT_DONE_%=; bra.uni WAIT_LOOP_%=; WAIT_DONE_%=: }" \
            :: "r"(_mbar), "r"(_parity) : "memory"); \
    } \
} while(0)

__device__ __forceinline__ void tma_load_2d(uint32_t dst_smem, const CUtensorMap* m,
                                            int x, int y, uint32_t mbar) {
    asm volatile(
        "cp.async.bulk.tensor.2d.shared::cta.global.tile.mbarrier::complete_tx::bytes "
        "[%0], [%1, {%2, %3}], [%4];"
        :: "r"(dst_smem), "l"(m), "r"(x), "r"(y), "r"(mbar) : "memory");
}

__device__ __forceinline__ void mma_bf16(float* d, const uint32_t* a, const uint32_t* b) {
    asm volatile(
        "mma.sync.aligned.m16n8k16.row.col.f32.bf16.bf16.f32 "
        "{%0,%1,%2,%3},{%4,%5,%6,%7},{%8,%9},{%0,%1,%2,%3};"
        : "+f"(d[0]), "+f"(d[1]), "+f"(d[2]), "+f"(d[3])
        : "r"(a[0]), "r"(a[1]), "r"(a[2]), "r"(a[3]), "r"(b[0]), "r"(b[1]));
}

__device__ __forceinline__ void ldsm_x4(uint32_t* r, uint32_t addr) {
    asm volatile("ldmatrix.sync.aligned.m8n8.x4.shared.b16 {%0,%1,%2,%3}, [%4];"
        : "=r"(r[0]), "=r"(r[1]), "=r"(r[2]), "=r"(r[3]) : "r"(addr));
}

__device__ __forceinline__ float ex2f(float x) {
    float y; asm("ex2.approx.f32 %0, %1;" : "=f"(y) : "f"(x)); return y;
}

__device__ __forceinline__ void split_one(float v, __nv_bfloat16& h, __nv_bfloat16& l) {
    h = __float2bfloat16_rn(v);
    l = __float2bfloat16_rn(v - __bfloat162float(h));
}
__device__ __forceinline__ void split_pack2(float a, float b, uint32_t& hi, uint32_t& lo) {
    __nv_bfloat16 ha, hb, la, lb;
    split_one(a, ha, la); split_one(b, hb, lb);
    __nv_bfloat162 ph = {ha, hb}, pl = {la, lb};
    hi = *(uint32_t*)&ph; lo = *(uint32_t*)&pl;
}

// ---------------- fp32 -> bf16 hi/lo split ------------------------------------
__global__ void __launch_bounds__(256) cvt_kernel(
    const float* __restrict__ x, __nv_bfloat16* __restrict__ hi,
    __nv_bfloat16* __restrict__ lo, int n4)
{
    int i = blockIdx.x * blockDim.x + threadIdx.x;
    if (i >= n4) return;
    float4 v = ((const float4*)x)[i];
    uint2 uh, ul;
    split_pack2(v.x, v.y, uh.x, ul.x);
    split_pack2(v.z, v.w, uh.y, ul.y);
    ((uint2*)hi)[i] = uh;
    ((uint2*)lo)[i] = ul;
}

// ---------------- split-bf16 GEMM mainloop (TMA + ldmatrix + mma.sync) -------
#define STAGE_BYTES 65536
#define T_AHI 0
#define T_ALO 16384
#define T_BHI 32768
#define T_BLO 49152
#define GEMM_SMEM (2*STAGE_BYTES + 32)

__device__ __forceinline__ void gemm_mainloop(
    const CUtensorMap* mAhi, const CUtensorMap* mAlo,
    const CUtensorMap* mBhi, const CUtensorMap* mBlo,
    int bm, int bn, int nst, char* smem, float acc[][8][4])
{
    const uint32_t sbase = smem_to_u32(smem);
    const uint32_t mb0 = sbase + 2 * STAGE_BYTES;
    const uint32_t mb1 = mb0 + 8;
    const int tid = threadIdx.x;
    const int wid = tid >> 5;
    const int lane = tid & 31;
    const int wm = wid & 3;
    const int wn = wid >> 2;

    if (tid == 0) {
        MBARRIER_INIT(mb0, 1);
        MBARRIER_INIT(mb1, 1);
    }
    FENCE_ASYNC_SHARED();
    __syncthreads();

    if (tid == 0) {
#pragma unroll
        for (int s = 0; s < 2; s++) {
            uint32_t mb = (s == 0) ? mb0 : mb1;
            uint32_t dst = sbase + s * STAGE_BYTES;
            MBARRIER_EXPECT_TX(mb, STAGE_BYTES);
            tma_load_2d(dst + T_AHI, mAhi, s * 64, bm, mb);
            tma_load_2d(dst + T_ALO, mAlo, s * 64, bm, mb);
            tma_load_2d(dst + T_BHI, mBhi, s * 64, bn, mb);
            tma_load_2d(dst + T_BLO, mBlo, s * 64, bn, mb);
        }
    }

    // ldmatrix lane geometry
    const uint32_t m16 = (lane & 7) * 16;
    const int rA = (lane & 7) + ((lane >> 3) & 1) * 8;
    const uint32_t hA = ((lane >> 4) & 1) * 16;
    const int rB = (lane & 7) + ((lane >> 4) & 1) * 8;
    const uint32_t hB = ((lane >> 3) & 1) * 16;
    uint32_t aoff[2], boff[4];
#pragma unroll
    for (int t = 0; t < 2; t++) aoff[t] = (uint32_t)(wm * 32 + t * 16 + rA) * 128;
#pragma unroll
    for (int jp = 0; jp < 4; jp++) boff[jp] = (uint32_t)(wn * 64 + jp * 16 + rB) * 128;

    for (int s = 0; s < nst; s++) {
        MBARRIER_WAIT_PARITY((s & 1) ? mb1 : mb0, (s >> 1) & 1);
        const uint32_t sb = sbase + (s & 1) * STAGE_BYTES;

#pragma unroll
        for (int ks = 0; ks < 4; ks++) {
            const uint32_t cA = (ks * 32 + hA) ^ m16;
            const uint32_t cB = (ks * 32 + hB) ^ m16;
            uint32_t ah[2][4], al[2][4];
#pragma unroll
            for (int t = 0; t < 2; t++) {
                ldsm_x4(ah[t], sb + T_AHI + aoff[t] + cA);
                ldsm_x4(al[t], sb + T_ALO + aoff[t] + cA);
            }
            uint32_t bh[4][4], bl[4][4];
#pragma unroll
            for (int jp = 0; jp < 4; jp++) {
                ldsm_x4(bh[jp], sb + T_BHI + boff[jp] + cB);
                ldsm_x4(bl[jp], sb + T_BLO + boff[jp] + cB);
            }
#pragma unroll
            for (int t = 0; t < 2; t++)
#pragma unroll
                for (int jp = 0; jp < 4; jp++) {
                    mma_bf16(acc[t][2*jp],   ah[t], &bh[jp][0]);
                    mma_bf16(acc[t][2*jp],   ah[t], &bl[jp][0]);
                    mma_bf16(acc[t][2*jp],   al[t], &bh[jp][0]);
                    mma_bf16(acc[t][2*jp+1], ah[t], &bh[jp][2]);
                    mma_bf16(acc[t][2*jp+1], ah[t], &bl[jp][2]);
                    mma_bf16(acc[t][2*jp+1], al[t], &bh[jp][2]);
                }
        }

        __syncthreads();
        if (tid == 0 && s + 2 < nst) {
            uint32_t mb = (s & 1) ? mb1 : mb0;
            uint32_t dst = sbase + (s & 1) * STAGE_BYTES;
            MBARRIER_EXPECT_TX(mb, STAGE_BYTES);
            tma_load_2d(dst + T_AHI, mAhi, (s + 2) * 64, bm, mb);
            tma_load_2d(dst + T_ALO, mAlo, (s + 2) * 64, bm, mb);
            tma_load_2d(dst + T_BHI, mBhi, (s + 2) * 64, bn, mb);
            tma_load_2d(dst + T_BLO, mBlo, (s + 2) * 64, bn, mb);
        }
    }
}

// ---------------- generic GEMM kernel -----------------------------------------
template<int WRITE_F32, int WRITE_HILO, int RELU>
__global__ void __launch_bounds__(256, 1) gemm_mma_kernel(
    const __grid_constant__ CUtensorMap mAhi,
    const __grid_constant__ CUtensorMap mAlo,
    const __grid_constant__ CUtensorMap mBhi,
    const __grid_constant__ CUtensorMap mBlo,
    const float* __restrict__ bias,
    float* __restrict__ C, __nv_bfloat16* __restrict__ Chi, __nv_bfloat16* __restrict__ Clo,
    int N, int K)
{
    extern __shared__ char smem[];
    const int bm = blockIdx.y * 128;
    const int bn = blockIdx.x * 128;
    float acc[2][8][4];
#pragma unroll
    for (int t = 0; t < 2; t++)
#pragma unroll
        for (int j = 0; j < 8; j++)
#pragma unroll
            for (int q = 0; q < 4; q++) acc[t][j][q] = 0.f;

    gemm_mainloop(&mAhi, &mAlo, &mBhi, &mBlo, bm, bn, K >> 6, smem, acc);

    const int lane = threadIdx.x & 31;
    const int wid = threadIdx.x >> 5;
    const int g = lane >> 2, tq = lane & 3;
    const int wm = wid & 3, wn = wid >> 2;
#pragma unroll
    for (int t = 0; t < 2; t++) {
        int row = bm + wm * 32 + t * 16 + g;
#pragma unroll
        for (int j = 0; j < 8; j++) {
            int col = bn + wn * 64 + j * 8 + tq * 2;
            float2 bj = *(const float2*)&bias[col];
            float v0 = acc[t][j][0] + bj.x;
            float v1 = acc[t][j][1] + bj.y;
            float v2 = acc[t][j][2] + bj.x;
            float v3 = acc[t][j][3] + bj.y;
            if (RELU) {
                v0 = fmaxf(v0, 0.f); v1 = fmaxf(v1, 0.f);
                v2 = fmaxf(v2, 0.f); v3 = fmaxf(v3, 0.f);
            }
            if (WRITE_F32) {
                *(float2*)&C[(size_t)row * N + col]       = make_float2(v0, v1);
                *(float2*)&C[(size_t)(row + 8) * N + col] = make_float2(v2, v3);
            }
            if (WRITE_HILO) {
                uint32_t h01, l01, h23, l23;
                split_pack2(v0, v1, h01, l01);
                split_pack2(v2, v3, h23, l23);
                *(uint32_t*)&Chi[(size_t)row * N + col]       = h01;
                *(uint32_t*)&Chi[(size_t)(row + 8) * N + col] = h23;
                *(uint32_t*)&Clo[(size_t)row * N + col]       = l01;
                *(uint32_t*)&Clo[(size_t)(row + 8) * N + col] = l23;
            }
        }
    }
}

// ---------------- fused QKV GEMM (N=3072 packed weight; scatter epilogue) ----
__global__ void __launch_bounds__(256, 1) gemm_qkv_kernel(
    const __grid_constant__ CUtensorMap mAhi,
    const __grid_constant__ CUtensorMap mAlo,
    const __grid_constant__ CUtensorMap mBhi,
    const __grid_constant__ CUtensorMap mBlo,
    const float* __restrict__ bQ, const float* __restrict__ bK, const float* __restrict__ bV,
    __nv_bfloat16* __restrict__ Qhi, __nv_bfloat16* __restrict__ Qlo,
    __nv_bfloat16* __restrict__ Khi, __nv_bfloat16* __restrict__ Klo,
    __nv_bfloat16* __restrict__ Vhi, __nv_bfloat16* __restrict__ Vlo)
{
    extern __shared__ char smem[];
    const int bm = blockIdx.y * 128;
    const int bn = blockIdx.x * 128;   // 0..2944 within 3072
    float acc[2][8][4];
#pragma unroll
    for (int t = 0; t < 2; t++)
#pragma unroll
        for (int j = 0; j < 8; j++)
#pragma unroll
            for (int q = 0; q < 4; q++) acc[t][j][q] = 0.f;

    gemm_mainloop(&mAhi, &mAlo, &mBhi, &mBlo, bm, bn, DMODEL >> 6, smem, acc);

    const int part = blockIdx.x >> 3;          // 0=Q 1=K 2=V
    const int nb = (blockIdx.x & 7) * 128;     // col base within part
    const float* bias = (part == 0) ? bQ : (part == 1) ? bK : bV;
    __nv_bfloat16* Ohi = (part == 0) ? Qhi : (part == 1) ? Khi : Vhi;
    __nv_bfloat16* Olo = (part == 0) ? Qlo : (part == 1) ? Klo : Vlo;
    const float scl = (part == 0) ? QSCALE : 1.0f;

    const int lane = threadIdx.x & 31;
    const int wid = threadIdx.x >> 5;
    const int g = lane >> 2, tq = lane & 3;
    const int wm = wid & 3, wn = wid >> 2;
#pragma unroll
    for (int t = 0; t < 2; t++) {
        int row = bm + wm * 32 + t * 16 + g;
#pragma unroll
        for (int j = 0; j < 8; j++) {
            int col = nb + wn * 64 + j * 8 + tq * 2;
            float2 bj = *(const float2*)&bias[col];
            float v0 = (acc[t][j][0] + bj.x) * scl;
            float v1 = (acc[t][j][1] + bj.y) * scl;
            float v2 = (acc[t][j][2] + bj.x) * scl;
            float v3 = (acc[t][j][3] + bj.y) * scl;
            uint32_t h01, l01, h23, l23;
            split_pack2(v0, v1, h01, l01);
            split_pack2(v2, v3, h23, l23);
            *(uint32_t*)&Ohi[(size_t)row * DMODEL + col]       = h01;
            *(uint32_t*)&Ohi[(size_t)(row + 8) * DMODEL + col] = h23;
            *(uint32_t*)&Olo[(size_t)row * DMODEL + col]       = l01;
            *(uint32_t*)&Olo[(size_t)(row + 8) * DMODEL + col] = l23;
        }
    }
}

// ---------------- V transpose: V[s*4+b][d] -> VT[(b*DM+d)][s] -----------------
__global__ void __launch_bounds__(256) transpose_v_kernel(
    const __nv_bfloat16* __restrict__ Vhi, const __nv_bfloat16* __restrict__ Vlo,
    __nv_bfloat16* __restrict__ VThi, __nv_bfloat16* __restrict__ VTlo)
{
    __shared__ __nv_bfloat16 sh[32][64 + 4];
    __shared__ __nv_bfloat16 sl[32][64 + 4];
    const int tid = threadIdx.x;
    const int s0 = blockIdx.x * 32;
    const int d0 = blockIdx.y * 64;
    const int b  = blockIdx.z;

#pragma unroll
    for (int p = 0; p < 2; p++) {
        int idx = tid + p * 256;
        int srow = idx >> 4;
        int dq = idx & 15;
        size_t ga = ((size_t)(s0 + srow) * BATCH + b) * DMODEL + d0 + dq * 4;
        uint2 vh = *(const uint2*)(Vhi + ga);
        uint2 vl = *(const uint2*)(Vlo + ga);
        *(uint2*)&sh[srow][dq * 4] = vh;
        *(uint2*)&sl[srow][dq * 4] = vl;
    }
    __syncthreads();
#pragma unroll
    for (int p = 0; p < 2; p++) {
        int idx = tid + p * 256;
        int drow = idx >> 3;
        int sq = idx & 7;
        __nv_bfloat16 oh[4], ol[4];
#pragma unroll
        for (int k = 0; k < 4; k++) {
            oh[k] = sh[sq * 4 + k][drow];
            ol[k] = sl[sq * 4 + k][drow];
        }
        size_t ga = ((size_t)(b * DMODEL + d0 + drow)) * SLEN + s0 + sq * 4;
        *(uint2*)(VThi + ga) = *(uint2*)oh;
        *(uint2*)(VTlo + ga) = *(uint2*)ol;
    }
}

// ---------------- Flash attention (ldmatrix + mma.sync + exp2 domain) --------
#define ATT_QHI 0
#define ATT_QLO 16384
#define ATT_ST0 32768
#define ATT_STSZ 32768
#define ATT_CTRL (ATT_ST0 + 2*ATT_STSZ)
#define ATT_SMEM (ATT_CTRL + 64)
#define NKT (SLEN/64)

__global__ void __launch_bounds__(256, 2) attn_mma_kernel(
    const __grid_constant__ CUtensorMap mQhi, const __grid_constant__ CUtensorMap mQlo,
    const __grid_constant__ CUtensorMap mKhi, const __grid_constant__ CUtensorMap mKlo,
    const __grid_constant__ CUtensorMap mVhi, const __grid_constant__ CUtensorMap mVlo,
    __nv_bfloat16* __restrict__ Ohi, __nv_bfloat16* __restrict__ Olo)
{
    extern __shared__ char smem[];
    const uint32_t sbase = smem_to_u32(smem);
    const uint32_t mb0 = sbase + ATT_CTRL;
    const uint32_t mb1 = mb0 + 8;
    const int tid = threadIdx.x;
    const int w = tid >> 5;
    const int lane = tid & 31;
    const int g = lane >> 2;
    const int t = lane & 3;
    const int q0 = blockIdx.x * 128;
    const int b = blockIdx.y >> 4;
    const int h = blockIdx.y & 15;
    const int xqk = b * DMODEL + h * 64;

    if (tid == 0) {
        MBARRIER_INIT(mb0, 1);
        MBARRIER_INIT(mb1, 1);
    }
    FENCE_ASYNC_SHARED();
    __syncthreads();

    if (tid == 0) {
        MBARRIER_EXPECT_TX(mb0, ATT_STSZ + 32768);
        tma_load_2d(sbase + ATT_QHI, &mQhi, xqk, q0, mb0);
        tma_load_2d(sbase + ATT_QLO, &mQlo, xqk, q0, mb0);
        tma_load_2d(sbase + ATT_ST0 + 0,     &mKhi, xqk, 0, mb0);
        tma_load_2d(sbase + ATT_ST0 + 8192,  &mKlo, xqk, 0, mb0);
        tma_load_2d(sbase + ATT_ST0 + 16384, &mVhi, 0, xqk, mb0);
        tma_load_2d(sbase + ATT_ST0 + 24576, &mVlo, 0, xqk, mb0);
        MBARRIER_EXPECT_TX(mb1, ATT_STSZ);
        tma_load_2d(sbase + ATT_ST0 + ATT_STSZ + 0,     &mKhi, xqk, 64, mb1);
        tma_load_2d(sbase + ATT_ST0 + ATT_STSZ + 8192,  &mKlo, xqk, 64, mb1);
        tma_load_2d(sbase + ATT_ST0 + ATT_STSZ + 16384, &mVhi, 64, xqk, mb1);
        tma_load_2d(sbase + ATT_ST0 + ATT_STSZ + 24576, &mVlo, 64, xqk, mb1);
    }

    // ldmatrix lane geometry
    const uint32_t m16 = (lane & 7) * 16;
    const int rA = (lane & 7) + ((lane >> 3) & 1) * 8;
    const uint32_t hA = ((lane >> 4) & 1) * 16;
    const int rB = (lane & 7) + ((lane >> 4) & 1) * 8;
    const uint32_t hB = ((lane >> 3) & 1) * 16;
    const uint32_t qoff = (uint32_t)(w * 16 + rA) * 128;
    uint32_t kvoff[4];
#pragma unroll
    for (int jp = 0; jp < 4; jp++) kvoff[jp] = (uint32_t)(jp * 16 + rB) * 128;

    float m_i[2] = {-1e30f, -1e30f};
    float l_i[2] = {0.f, 0.f};
    float acc[8][4];
#pragma unroll
    for (int j = 0; j < 8; j++)
#pragma unroll
        for (int q = 0; q < 4; q++) acc[j][q] = 0.f;

    for (int s = 0; s < NKT; s++) {
        MBARRIER_WAIT_PARITY((s & 1) ? mb1 : mb0, (s >> 1) & 1);
        const uint32_t Kbu = sbase + ATT_ST0 + (s & 1) * ATT_STSZ;
        const uint32_t Vbu = Kbu + 16384;

        // ---- scores (log2 domain; 0.125*log2e pre-folded into Q) ----
        float sc[8][4];
#pragma unroll
        for (int j = 0; j < 8; j++)
#pragma unroll
            for (int q = 0; q < 4; q++) sc[j][q] = 0.f;

#pragma unroll
        for (int ks = 0; ks < 4; ks++) {
            const uint32_t cA = (ks * 32 + hA) ^ m16;
            const uint32_t cB = (ks * 32 + hB) ^ m16;
            uint32_t qh[4], ql[4];
            ldsm_x4(qh, sbase + ATT_QHI + qoff + cA);
            ldsm_x4(ql, sbase + ATT_QLO + qoff + cA);
#pragma unroll
            for (int jp = 0; jp < 4; jp++) {
                uint32_t kh[4], kl[4];
                ldsm_x4(kh, Kbu + kvoff[jp] + cB);
                ldsm_x4(kl, Kbu + 8192 + kvoff[jp] + cB);
                mma_bf16(sc[2*jp],   qh, &kh[0]);
                mma_bf16(sc[2*jp],   qh, &kl[0]);
                mma_bf16(sc[2*jp],   ql, &kh[0]);
                mma_bf16(sc[2*jp+1], qh, &kh[2]);
                mma_bf16(sc[2*jp+1], qh, &kl[2]);
                mma_bf16(sc[2*jp+1], ql, &kh[2]);
            }
        }

        // ---- online softmax (log2 domain) ----
        float mx0 = -1e30f, mx1 = -1e30f;
#pragma unroll
        for (int j = 0; j < 8; j++) {
            mx0 = fmaxf(mx0, fmaxf(sc[j][0], sc[j][1]));
            mx1 = fmaxf(mx1, fmaxf(sc[j][2], sc[j][3]));
        }
        mx0 = fmaxf(mx0, __shfl_xor_sync(0xffffffffu, mx0, 1));
        mx0 = fmaxf(mx0, __shfl_xor_sync(0xffffffffu, mx0, 2));
        mx1 = fmaxf(mx1, __shfl_xor_sync(0xffffffffu, mx1, 1));
        mx1 = fmaxf(mx1, __shfl_xor_sync(0xffffffffu, mx1, 2));
        float mn0 = fmaxf(m_i[0], mx0);
        float mn1 = fmaxf(m_i[1], mx1);
        float a0 = ex2f(m_i[0] - mn0);
        float a1 = ex2f(m_i[1] - mn1);
        m_i[0] = mn0; m_i[1] = mn1;
        float s0 = 0.f, s1 = 0.f;
#pragma unroll
        for (int j = 0; j < 8; j++) {
            sc[j][0] = ex2f(sc[j][0] - mn0);
            sc[j][1] = ex2f(sc[j][1] - mn0);
            sc[j][2] = ex2f(sc[j][2] - mn1);
            sc[j][3] = ex2f(sc[j][3] - mn1);
            s0 += sc[j][0] + sc[j][1];
            s1 += sc[j][2] + sc[j][3];
        }
        s0 += __shfl_xor_sync(0xffffffffu, s0, 1);
        s0 += __shfl_xor_sync(0xffffffffu, s0, 2);
        s1 += __shfl_xor_sync(0xffffffffu, s1, 1);
        s1 += __shfl_xor_sync(0xffffffffu, s1, 2);
        l_i[0] = l_i[0] * a0 + s0;
        l_i[1] = l_i[1] * a1 + s1;
#pragma unroll
        for (int j = 0; j < 8; j++) {
            acc[j][0] *= a0; acc[j][1] *= a0;
            acc[j][2] *= a1; acc[j][3] *= a1;
        }

        // ---- ctx += P V (P split in registers) ----
#pragma unroll
        for (int ks = 0; ks < 4; ks++) {
            uint32_t pah[4], pal[4];
            split_pack2(sc[2*ks][0],   sc[2*ks][1],   pah[0], pal[0]);
            split_pack2(sc[2*ks][2],   sc[2*ks][3],   pah[1], pal[1]);
            split_pack2(sc[2*ks+1][0], sc[2*ks+1][1], pah[2], pal[2]);
            split_pack2(sc[2*ks+1][2], sc[2*ks+1][3], pah[3], pal[3]);
            const uint32_t cB = (ks * 32 + hB) ^ m16;
#pragma unroll
            for (int jp = 0; jp < 4; jp++) {
                uint32_t vh[4], vl[4];
                ldsm_x4(vh, Vbu + kvoff[jp] + cB);
                ldsm_x4(vl, Vbu + 8192 + kvoff[jp] + cB);
                mma_bf16(acc[2*jp],   pah, &vh[0]);
                mma_bf16(acc[2*jp],   pah, &vl[0]);
                mma_bf16(acc[2*jp],   pal, &vh[0]);
                mma_bf16(acc[2*jp+1], pah, &vh[2]);
                mma_bf16(acc[2*jp+1], pah, &vl[2]);
                mma_bf16(acc[2*jp+1], pal, &vh[2]);
            }
        }

        __syncthreads();
        if (tid == 0 && s + 2 < NKT) {
            uint32_t mb = (s & 1) ? mb1 : mb0;
            uint32_t dst = sbase + ATT_ST0 + (s & 1) * ATT_STSZ;
            MBARRIER_EXPECT_TX(mb, ATT_STSZ);
            tma_load_2d(dst + 0,     &mKhi, xqk, (s + 2) * 64, mb);
            tma_load_2d(dst + 8192,  &mKlo, xqk, (s + 2) * 64, mb);
            tma_load_2d(dst + 16384, &mVhi, (s + 2) * 64, xqk, mb);
            tma_load_2d(dst + 24576, &mVlo, (s + 2) * 64, xqk, mb);
        }
    }

    const float inv0 = 1.0f / l_i[0];
    const float inv1 = 1.0f / l_i[1];
    const int row0 = q0 + w * 16 + g;
    const int row1 = row0 + 8;
    const size_t tok0 = (size_t)row0 * BATCH + b;
    const size_t tok1 = (size_t)row1 * BATCH + b;
#pragma unroll
    for (int j = 0; j < 8; j++) {
        const int col = h * 64 + j * 8 + t * 2;
        uint32_t h01, l01, h23, l23;
        split_pack2(acc[j][0] * inv0, acc[j][1] * inv0, h01, l01);
        split_pack2(acc[j][2] * inv1, acc[j][3] * inv1, h23, l23);
        *(uint32_t*)&Ohi[tok0 * DMODEL + col] = h01;
        *(uint32_t*)&Olo[tok0 * DMODEL + col] = l01;
        *(uint32_t*)&Ohi[tok1 * DMODEL + col] = h23;
        *(uint32_t*)&Olo[tok1 * DMODEL + col] = l23;
    }
}

// ---------------- fused residual add + LayerNorm -----------------------------
template<int HILO>
__global__ void __launch_bounds__(256) add_ln_kernel(
    const float* __restrict__ A, const float* __restrict__ R,
    const float* __restrict__ gam, const float* __restrict__ bet,
    float* __restrict__ out, __nv_bfloat16* __restrict__ Ohi,
    __nv_bfloat16* __restrict__ Olo)
{
    __shared__ float red_s[8];
    __shared__ float red_ss[8];
    __shared__ float s_mu, s_rstd;
    const int row = blockIdx.x;
    const int t = threadIdx.x;
    const float4* a4 = (const float4*)(A + (size_t)row * DMODEL);
    const float4* r4 = (const float4*)(R + (size_t)row * DMODEL);
    float4 v = a4[t];
    float4 w = r4[t];
    v.x += w.x; v.y += w.y; v.z += w.z; v.w += w.w;
    float s = v.x + v.y + v.z + v.w;
    float ss = v.x * v.x + v.y * v.y + v.z * v.z + v.w * v.w;
#pragma unroll
    for (int off = 16; off >= 1; off >>= 1) {
        s  += __shfl_xor_sync(0xffffffffu, s, off);
        ss += __shfl_xor_sync(0xffffffffu, ss, off);
    }
    if ((t & 31) == 0) { red_s[t >> 5] = s; red_ss[t >> 5] = ss; }
    __syncthreads();
    if (t == 0) {
        float ts = 0.f, tss = 0.f;
#pragma unroll
        for (int i = 0; i < 8; i++) { ts += red_s[i]; tss += red_ss[i]; }
        float mu = ts * (1.0f / DMODEL);
        float var = tss * (1.0f / DMODEL) - mu * mu;
        s_mu = mu;
        s_rstd = rsqrtf(var + LN_EPS);
    }
    __syncthreads();
    float mu = s_mu, rs = s_rstd;
    float4 g = ((const float4*)gam)[t], bb = ((const float4*)bet)[t];
    float4 o;
    o.x = (v.x - mu) * rs * g.x + bb.x;
    o.y = (v.y - mu) * rs * g.y + bb.y;
    o.z = (v.z - mu) * rs * g.z + bb.z;
    o.w = (v.w - mu) * rs * g.w + bb.w;
    ((float4*)(out + (size_t)row * DMODEL))[t] = o;
    if (HILO) {
        uint2 uh, ul;
        split_pack2(o.x, o.y, uh.x, ul.x);
        split_pack2(o.z, o.w, uh.y, ul.y);
        ((uint2*)(Ohi + (size_t)row * DMODEL))[t] = uh;
        ((uint2*)(Olo + (size_t)row * DMODEL))[t] = ul;
    }
}

// ---------------- host: tensormap + launch ------------------------------------
typedef CUresult (*EncodeFn)(
    CUtensorMap*, CUtensorMapDataType, cuuint32_t, void*,
    const cuuint64_t*, const cuuint64_t*, const cuuint32_t*, const cuuint32_t*,
    CUtensorMapInterleave, CUtensorMapSwizzle, CUtensorMapL2promotion,
    CUtensorMapFloatOOBfill);

static void make_desc(EncodeFn enc, CUtensorMap* out, void* ptr,
                      uint64_t rows, uint64_t K, uint32_t box1)
{
    cuuint64_t dims[2]    = {K, rows};
    cuuint64_t strides[1] = {K * 2};
    cuuint32_t box[2]     = {64, box1};
    cuuint32_t estr[2]    = {1, 1};
    enc(out, CU_TENSOR_MAP_DATA_TYPE_BFLOAT16, 2, ptr, dims, strides, box, estr,
        CU_TENSOR_MAP_INTERLEAVE_NONE, CU_TENSOR_MAP_SWIZZLE_128B,
        CU_TENSOR_MAP_L2_PROMOTION_L2_128B, CU_TENSOR_MAP_FLOAT_OOB_FILL_NONE);
}

extern "C" void kernel_launch(void* const* d_in, const int* in_sizes, int n_in,
                              void* d_out, int out_size)
{
    const float* X    = (const float*)d_in[0];
    const float* WQw  = (const float*)d_in[1];
    const float* WQb  = (const float*)d_in[2];
    const float* WKw  = (const float*)d_in[3];
    const float* WKb  = (const float*)d_in[4];
    const float* WVw  = (const float*)d_in[5];
    const float* WVb  = (const float*)d_in[6];
    const float* WOw  = (const float*)d_in[7];
    const float* WOb  = (const float*)d_in[8];
    const float* ln1g = (const float*)d_in[9];
    const float* ln1b = (const float*)d_in[10];
    const float* W1   = (const float*)d_in[11];
    const float* b1   = (const float*)d_in[12];
    const float* W2   = (const float*)d_in[13];
    const float* b2   = (const float*)d_in[14];
    const float* ln2g = (const float*)d_in[15];
    const float* ln2b = (const float*)d_in[16];
    float* out = (float*)d_out;

    float *Y, *X1, *M;
    cudaGetSymbolAddress((void**)&Y,  g_Y);
    cudaGetSymbolAddress((void**)&X1, g_X1);
    cudaGetSymbolAddress((void**)&M,  g_M);

    __nv_bfloat16 *Xhi,*Xlo,*X1hi,*X1lo,*CTXhi,*CTXlo,*HIDhi,*HIDlo;
    __nv_bfloat16 *Qhi,*Qlo,*Khi,*Klo,*Vhi,*Vlo,*VThi,*VTlo;
    __nv_bfloat16 *WQKVhi,*WQKVlo,*WOhi,*WOlo,*W1hi,*W1lo,*W2hi,*W2lo;
    cudaGetSymbolAddress((void**)&Xhi,  g_Xhi);  cudaGetSymbolAddress((void**)&Xlo,  g_Xlo);
    cudaGetSymbolAddress((void**)&X1hi, g_X1hi); cudaGetSymbolAddress((void**)&X1lo, g_X1lo);
    cudaGetSymbolAddress((void**)&CTXhi,g_CTXhi);cudaGetSymbolAddress((void**)&CTXlo,g_CTXlo);
    cudaGetSymbolAddress((void**)&Qhi,  g_Qhi);  cudaGetSymbolAddress((void**)&Qlo,  g_Qlo);
    cudaGetSymbolAddress((void**)&Khi,  g_Khi);  cudaGetSymbolAddress((void**)&Klo,  g_Klo);
    cudaGetSymbolAddress((void**)&Vhi,  g_Vhi);  cudaGetSymbolAddress((void**)&Vlo,  g_Vlo);
    cudaGetSymbolAddress((void**)&VThi, g_VThi); cudaGetSymbolAddress((void**)&VTlo, g_VTlo);
    cudaGetSymbolAddress((void**)&HIDhi,g_HIDhi);cudaGetSymbolAddress((void**)&HIDlo,g_HIDlo);
    cudaGetSymbolAddress((void**)&WQKVhi, g_WQKVhi); cudaGetSymbolAddress((void**)&WQKVlo, g_WQKVlo);
    cudaGetSymbolAddress((void**)&WOhi, g_WOhi); cudaGetSymbolAddress((void**)&WOlo, g_WOlo);
    cudaGetSymbolAddress((void**)&W1hi, g_W1hi); cudaGetSymbolAddress((void**)&W1lo, g_W1lo);
    cudaGetSymbolAddress((void**)&W2hi, g_W2hi); cudaGetSymbolAddress((void**)&W2lo, g_W2lo);

    EncodeFn enc = nullptr;
    {
        void* fp = nullptr;
        cudaDriverEntryPointQueryResult qr;
        cudaGetDriverEntryPoint("cuTensorMapEncodeTiled", &fp, cudaEnableDefault, &qr);
        enc = (EncodeFn)fp;
    }

    CUtensorMap dXhi, dXlo, dWQKVhi, dWQKVlo, dCTXhi, dCTXlo, dWOhi, dWOlo;
    CUtensorMap dX1hi, dX1lo, dW1hi, dW1lo, dHIDhi, dHIDlo, dW2hi, dW2lo;
    make_desc(enc, &dXhi,  Xhi,  NTOK, DMODEL, 128);  make_desc(enc, &dXlo,  Xlo,  NTOK, DMODEL, 128);
    make_desc(enc, &dWQKVhi, WQKVhi, 3*DMODEL, DMODEL, 128);
    make_desc(enc, &dWQKVlo, WQKVlo, 3*DMODEL, DMODEL, 128);
    make_desc(enc, &dCTXhi,CTXhi,NTOK, DMODEL, 128);  make_desc(enc, &dCTXlo,CTXlo,NTOK, DMODEL, 128);
    make_desc(enc, &dWOhi, WOhi, DMODEL, DMODEL, 128);make_desc(enc, &dWOlo, WOlo, DMODEL, DMODEL, 128);
    make_desc(enc, &dX1hi, X1hi, NTOK, DMODEL, 128);  make_desc(enc, &dX1lo, X1lo, NTOK, DMODEL, 128);
    make_desc(enc, &dW1hi, W1hi, DFFN, DMODEL, 128);  make_desc(enc, &dW1lo, W1lo, DFFN, DMODEL, 128);
    make_desc(enc, &dHIDhi,HIDhi,NTOK, DFFN, 128);    make_desc(enc, &dHIDlo,HIDlo,NTOK, DFFN, 128);
    make_desc(enc, &dW2hi, W2hi, DMODEL, DFFN, 128);  make_desc(enc, &dW2lo, W2lo, DMODEL, DFFN, 128);

    CUtensorMap dQhi, dQlo, dKhi, dKlo, dVThi, dVTlo;
    make_desc(enc, &dQhi, Qhi, SLEN, BATCH*DMODEL, 128);
    make_desc(enc, &dQlo, Qlo, SLEN, BATCH*DMODEL, 128);
    make_desc(enc, &dKhi, Khi, SLEN, BATCH*DMODEL, 64);
    make_desc(enc, &dKlo, Klo, SLEN, BATCH*DMODEL, 64);
    make_desc(enc, &dVThi, VThi, BATCH*DMODEL, SLEN, 64);
    make_desc(enc, &dVTlo, VTlo, BATCH*DMODEL, SLEN, 64);

    cudaFuncSetAttribute(gemm_mma_kernel<1,0,0>, cudaFuncAttributeMaxDynamicSharedMemorySize, GEMM_SMEM);
    cudaFuncSetAttribute(gemm_mma_kernel<0,1,1>, cudaFuncAttributeMaxDynamicSharedMemorySize, GEMM_SMEM);
    cudaFuncSetAttribute(gemm_qkv_kernel, cudaFuncAttributeMaxDynamicSharedMemorySize, GEMM_SMEM);
    cudaFuncSetAttribute(attn_mma_kernel, cudaFuncAttributeMaxDynamicSharedMemorySize, ATT_SMEM);

    // ---- fp32 -> bf16 hi/lo splits (WQ/WK/WV packed into one weight) ----
    cvt_kernel<<<(NTOK*DMODEL/4 + 255)/256, 256>>>(X,   Xhi,  Xlo,  NTOK*DMODEL/4);
    cvt_kernel<<<(DMODEL*DMODEL/4 + 255)/256, 256>>>(WQw, WQKVhi,                 WQKVlo,                 DMODEL*DMODEL/4);
    cvt_kernel<<<(DMODEL*DMODEL/4 + 255)/256, 256>>>(WKw, WQKVhi + DMODEL*DMODEL, WQKVlo + DMODEL*DMODEL, DMODEL*DMODEL/4);
    cvt_kernel<<<(DMODEL*DMODEL/4 + 255)/256, 256>>>(WVw, WQKVhi + 2*DMODEL*DMODEL, WQKVlo + 2*DMODEL*DMODEL, DMODEL*DMODEL/4);
    cvt_kernel<<<(DMODEL*DMODEL/4 + 255)/256, 256>>>(WOw, WOhi, WOlo, DMODEL*DMODEL/4);
    cvt_kernel<<<(DFFN*DMODEL/4 + 255)/256, 256>>>(W1,  W1hi, W1lo, DFFN*DMODEL/4);
    cvt_kernel<<<(DMODEL*DFFN/4 + 255)/256, 256>>>(W2,  W2hi, W2lo, DMODEL*DFFN/4);

    dim3 gProj(DMODEL / 128, NTOK / 128);   // 8 x 64
    dim3 gQKV(3 * DMODEL / 128, NTOK / 128);// 24 x 64
    dim3 gFF1(DFFN / 128, NTOK / 128);      // 32 x 64

    // ---- fused QKV projection (Q pre-scaled by 0.125*log2e) ----
    gemm_qkv_kernel<<<gQKV, 256, GEMM_SMEM>>>(dXhi, dXlo, dWQKVhi, dWQKVlo,
        WQb, WKb, WVb, Qhi, Qlo, Khi, Klo, Vhi, Vlo);

    // ---- V transpose for PV operand ----
    transpose_v_kernel<<<dim3(SLEN/32, DMODEL/64, BATCH), 256>>>(Vhi, Vlo, VThi, VTlo);

    // ---- attention ----
    attn_mma_kernel<<<dim3(SLEN/128, BATCH*NHEAD), 256, ATT_SMEM>>>(
        dQhi, dQlo, dKhi, dKlo, dVThi, dVTlo, CTXhi, CTXlo);

    // ---- output projection + residual LN1 ----
    gemm_mma_kernel<1,0,0><<<gProj, 256, GEMM_SMEM>>>(dCTXhi, dCTXlo, dWOhi, dWOlo, WOb, Y, nullptr, nullptr, DMODEL, DMODEL);
    add_ln_kernel<1><<<NTOK, 256>>>(Y, X, ln1g, ln1b, X1, X1hi, X1lo);

    // ---- MLP ----
    gemm_mma_kernel<0,1,1><<<gFF1, 256, GEMM_SMEM>>>(dX1hi, dX1lo, dW1hi, dW1lo, b1, nullptr, HIDhi, HIDlo, DFFN, DMODEL);
    gemm_mma_kernel<1,0,0><<<gProj, 256, GEMM_SMEM>>>(dHIDhi, dHIDlo, dW2hi, dW2lo, b2, M, nullptr, nullptr, DMODEL, DFFN);
    add_ln_kernel<0><<<NTOK, 256>>>(M, X1, ln2g, ln2b, out, nullptr, nullptr);
}